// round 1
// baseline (speedup 1.0000x reference)
#include <cuda_runtime.h>
#include <math.h>

// Problem constants
#define B_  4096
#define C_  128
#define T_  10
#define J_  22
#define H_  128
#define N_  220      // T_*J_ nodes per batch
#define WPAD 132     // padded row length for transposed W in smem

#define NG_ 55       // N_/4 node groups
#define HG_ 32       // H_/4 h groups
#define NTHREADS 512

static const long long SA_TOTAL = (long long)B_ * T_ * J_ * J_;   // 19,824,640
static const long long TA_TOTAL = (long long)B_ * J_ * T_ * T_;   // 9,011,200

// smem layout (floats):
//   X  [C_ * N_]      = 28160   : X[c*220 + n], n = t*J_ + j
//   Wt [C_ * WPAD]    = 16896   : Wt[c*132 + h]  (transposed, padded)
//   sS,dS,sT,dT [220 each] = 880
// total = 45,936 floats = 183,744 bytes

__device__ __forceinline__ void gemm_reduce_branch(
    const float* __restrict__ X,      // smem [C_*N_]
    const float* __restrict__ Wt,     // smem [C_*WPAD]
    const float* __restrict__ aS,     // global [H_]
    const float* __restrict__ aD,     // global [H_]
    float* __restrict__ sArr,         // smem [N_]
    float* __restrict__ dArr,         // smem [N_]
    int tid)
{
    const int hg = tid >> 4;          // 0..31
    const int nc = tid & 15;          // 0..15

    // per-thread a values (L1-resident broadcast loads)
    const float a0s = aS[4*hg+0], a1s = aS[4*hg+1], a2s = aS[4*hg+2], a3s = aS[4*hg+3];
    const float a0d = aD[4*hg+0], a1d = aD[4*hg+1], a2d = aD[4*hg+2], a3d = aD[4*hg+3];

    for (int it = 0; it < 4; ++it) {
        const int ng = nc + (it << 4);
        if (ng >= NG_) break;

        float acc00=0.f,acc01=0.f,acc02=0.f,acc03=0.f;
        float acc10=0.f,acc11=0.f,acc12=0.f,acc13=0.f;
        float acc20=0.f,acc21=0.f,acc22=0.f,acc23=0.f;
        float acc30=0.f,acc31=0.f,acc32=0.f,acc33=0.f;

        const float* wp = Wt + (hg << 2);
        const float* xp = X  + (ng << 2);

        #pragma unroll 4
        for (int c = 0; c < C_; ++c) {
            const float4 wv = *(const float4*)(wp + c * WPAD);
            const float4 xv = *(const float4*)(xp + c * N_);
            acc00 = fmaf(wv.x, xv.x, acc00);
            acc01 = fmaf(wv.x, xv.y, acc01);
            acc02 = fmaf(wv.x, xv.z, acc02);
            acc03 = fmaf(wv.x, xv.w, acc03);
            acc10 = fmaf(wv.y, xv.x, acc10);
            acc11 = fmaf(wv.y, xv.y, acc11);
            acc12 = fmaf(wv.y, xv.z, acc12);
            acc13 = fmaf(wv.y, xv.w, acc13);
            acc20 = fmaf(wv.z, xv.x, acc20);
            acc21 = fmaf(wv.z, xv.y, acc21);
            acc22 = fmaf(wv.z, xv.z, acc22);
            acc23 = fmaf(wv.z, xv.w, acc23);
            acc30 = fmaf(wv.w, xv.x, acc30);
            acc31 = fmaf(wv.w, xv.y, acc31);
            acc32 = fmaf(wv.w, xv.z, acc32);
            acc33 = fmaf(wv.w, xv.w, acc33);
        }

        // LeakyReLU(0.2) then weighted reduce over the 4 h values
        #define LK(v) ((v) >= 0.f ? (v) : 0.2f * (v))
        float s0, s1, s2, s3, d0, d1, d2, d3, v;
        v = LK(acc00); s0 = a0s*v; d0 = a0d*v;
        v = LK(acc01); s1 = a0s*v; d1 = a0d*v;
        v = LK(acc02); s2 = a0s*v; d2 = a0d*v;
        v = LK(acc03); s3 = a0s*v; d3 = a0d*v;
        v = LK(acc10); s0 = fmaf(a1s,v,s0); d0 = fmaf(a1d,v,d0);
        v = LK(acc11); s1 = fmaf(a1s,v,s1); d1 = fmaf(a1d,v,d1);
        v = LK(acc12); s2 = fmaf(a1s,v,s2); d2 = fmaf(a1d,v,d2);
        v = LK(acc13); s3 = fmaf(a1s,v,s3); d3 = fmaf(a1d,v,d3);
        v = LK(acc20); s0 = fmaf(a2s,v,s0); d0 = fmaf(a2d,v,d0);
        v = LK(acc21); s1 = fmaf(a2s,v,s1); d1 = fmaf(a2d,v,d1);
        v = LK(acc22); s2 = fmaf(a2s,v,s2); d2 = fmaf(a2d,v,d2);
        v = LK(acc23); s3 = fmaf(a2s,v,s3); d3 = fmaf(a2d,v,d3);
        v = LK(acc30); s0 = fmaf(a3s,v,s0); d0 = fmaf(a3d,v,d0);
        v = LK(acc31); s1 = fmaf(a3s,v,s1); d1 = fmaf(a3d,v,d1);
        v = LK(acc32); s2 = fmaf(a3s,v,s2); d2 = fmaf(a3d,v,d2);
        v = LK(acc33); s3 = fmaf(a3s,v,s3); d3 = fmaf(a3d,v,d3);
        #undef LK

        const int n0 = ng << 2;
        atomicAdd(&sArr[n0+0], s0);
        atomicAdd(&sArr[n0+1], s1);
        atomicAdd(&sArr[n0+2], s2);
        atomicAdd(&sArr[n0+3], s3);
        atomicAdd(&dArr[n0+0], d0);
        atomicAdd(&dArr[n0+1], d1);
        atomicAdd(&dArr[n0+2], d2);
        atomicAdd(&dArr[n0+3], d3);
    }
}

__global__ void __launch_bounds__(NTHREADS, 1)
dms_st_attention_kernel(
    const float* __restrict__ src,
    const float* __restrict__ W_s,
    const float* __restrict__ a_src_s,
    const float* __restrict__ a_dst_s,
    const float* __restrict__ W_t,
    const float* __restrict__ a_src_t,
    const float* __restrict__ a_dst_t,
    const float* __restrict__ sa_bias,
    const float* __restrict__ ta_bias,
    float* __restrict__ out,
    long long out_size)
{
    extern __shared__ float sm[];
    float* X   = sm;                    // 28160
    float* Wt  = X + C_ * N_;           // 16896
    float* sS  = Wt + C_ * WPAD;        // 220
    float* dS  = sS + N_;
    float* sT  = dS + N_;
    float* dT  = sT + N_;

    const int tid = threadIdx.x;
    const int b   = blockIdx.x;

    // ---- Phase 0: load X tile (coalesced float4 copy), zero s/d arrays ----
    {
        const float4* g = (const float4*)(src + (size_t)b * (C_ * N_));
        float4* s4 = (float4*)X;
        const int n4 = (C_ * N_) / 4;   // 7040
        for (int i = tid; i < n4; i += NTHREADS) s4[i] = g[i];
        for (int i = tid; i < 4 * N_; i += NTHREADS) sS[i] = 0.f;  // covers sS,dS,sT,dT
    }

    // ---- Phase 1: spatial branch ----
    for (int i = tid; i < H_ * C_; i += NTHREADS) {
        int h = i >> 7, c = i & 127;
        Wt[c * WPAD + h] = W_s[i];
    }
    __syncthreads();
    gemm_reduce_branch(X, Wt, a_src_s, a_dst_s, sS, dS, tid);
    __syncthreads();

    // ---- Phase 2: temporal branch ----
    for (int i = tid; i < H_ * C_; i += NTHREADS) {
        int h = i >> 7, c = i & 127;
        Wt[c * WPAD + h] = W_t[i];
    }
    __syncthreads();
    gemm_reduce_branch(X, Wt, a_src_t, a_dst_t, sT, dT, tid);
    __syncthreads();

    // ---- Phase 3: softmax + bias + store ----
    // Spatial: 220 rows, row r = t*J_ + i, softmax over j (22)
    if (tid < N_) {
        const int r = tid;
        const int t = r / J_;
        const int i = r - t * J_;
        const float si = sS[r];
        const float* drow = dS + t * J_;
        float mx = -INFINITY;
        #pragma unroll
        for (int j = 0; j < J_; ++j) {
            float e = si + drow[j];
            mx = fmaxf(mx, e);
        }
        float ev[J_];
        float sum = 0.f;
        #pragma unroll
        for (int j = 0; j < J_; ++j) {
            ev[j] = expf(si + drow[j] - mx);
            sum += ev[j];
        }
        const float inv = 1.f / sum;
        float* o = out + ((size_t)b * N_ + r) * J_;
        const float* bias = sa_bias + i * J_;
        #pragma unroll
        for (int j = 0; j < J_; ++j)
            o[j] = ev[j] * inv + bias[j];
    }

    // Temporal: 220 rows, row r = j*T_ + ti, softmax over tj (10)
    if (tid < N_) {
        const int r  = tid;
        const int j  = r / T_;
        const int ti = r - j * T_;
        const float si = sT[ti * J_ + j];
        float mx = -INFINITY;
        #pragma unroll
        for (int tj = 0; tj < T_; ++tj) {
            float e = si + dT[tj * J_ + j];
            mx = fmaxf(mx, e);
        }
        float ev[T_];
        float sum = 0.f;
        #pragma unroll
        for (int tj = 0; tj < T_; ++tj) {
            ev[tj] = expf(si + dT[tj * J_ + j] - mx);
            sum += ev[tj];
        }
        const float inv = 1.f / sum;
        float* o = out + SA_TOTAL + ((size_t)b * N_ + r) * T_;
        const float* bias = ta_bias + ti * T_;
        #pragma unroll
        for (int tj = 0; tj < T_; ++tj)
            o[tj] = ev[tj] * inv + bias[tj];
    }

    // ---- Tail: the 4 scalar zeros (and any padding) ----
    if (b == 0) {
        for (long long i = SA_TOTAL + TA_TOTAL + tid; i < out_size; i += NTHREADS)
            out[i] = 0.f;
    }
}

extern "C" void kernel_launch(void* const* d_in, const int* in_sizes, int n_in,
                              void* d_out, int out_size)
{
    const float* src     = (const float*)d_in[0];
    const float* W_s     = (const float*)d_in[1];
    const float* a_src_s = (const float*)d_in[2];
    const float* a_dst_s = (const float*)d_in[3];
    const float* W_t     = (const float*)d_in[4];
    const float* a_src_t = (const float*)d_in[5];
    const float* a_dst_t = (const float*)d_in[6];
    const float* sa_bias = (const float*)d_in[7];
    const float* ta_bias = (const float*)d_in[8];
    float* out = (float*)d_out;

    const int smem_bytes = (C_ * N_ + C_ * WPAD + 4 * N_) * sizeof(float); // 183,744

    cudaFuncSetAttribute(dms_st_attention_kernel,
                         cudaFuncAttributeMaxDynamicSharedMemorySize, smem_bytes);

    dms_st_attention_kernel<<<B_, NTHREADS, smem_bytes>>>(
        src, W_s, a_src_s, a_dst_s, W_t, a_src_t, a_dst_t,
        sa_bias, ta_bias, out, (long long)out_size);
}

// round 2
// speedup vs baseline: 1.4211x; 1.4211x over previous
#include <cuda_runtime.h>
#include <math.h>

#define B_  4096
#define C_  128
#define T_  10
#define J_  22
#define N_  220
#define NP_ 256      // padded node count
#define H_  128
#define WSTR 132     // Wt smem row stride (16B-aligned rows)
#define NTHREADS 512

typedef unsigned long long ull;

static const long long SA_TOTAL = (long long)B_ * T_ * J_ * J_;   // 19,824,640
static const long long TA_TOTAL = (long long)B_ * J_ * T_ * T_;   //  9,011,200

// smem floats:
//   X  [128*256] = 32768
//   Wt [128*132] = 16896   (reused between mainloops as partial buffers Ps/Pd)
//   sS,dS,sT,dT [256 each] = 1024
// total = 50688 floats = 202,752 bytes

__device__ __forceinline__ ull splat2(float a) {
    ull r; asm("mov.b64 %0, {%1, %1};" : "=l"(r) : "f"(a)); return r;
}
__device__ __forceinline__ ull fma2(ull a, ull b, ull c) {
    ull d; asm("fma.rn.f32x2 %0, %1, %2, %3;" : "=l"(d) : "l"(a), "l"(b), "l"(c)); return d;
}

__global__ void __launch_bounds__(NTHREADS, 1)
dms_st_attention_kernel(
    const float* __restrict__ src,
    const float* __restrict__ W_s,
    const float* __restrict__ a_src_s,
    const float* __restrict__ a_dst_s,
    const float* __restrict__ W_t,
    const float* __restrict__ a_src_t,
    const float* __restrict__ a_dst_t,
    const float* __restrict__ sa_bias,
    const float* __restrict__ ta_bias,
    float* __restrict__ out,
    long long out_size)
{
    extern __shared__ float sm[];
    float* X  = sm;                 // 32768
    float* Wt = X + C_ * NP_;       // 16896
    float* sS = Wt + C_ * WSTR;
    float* dS = sS + NP_;
    float* sT = dS + NP_;
    float* dT = sT + NP_;

    const int tid = threadIdx.x;
    const int b   = blockIdx.x;
    const int hg  = tid >> 5;       // 0..15 : h block of 8
    const int ng  = tid & 31;       // 0..31 : n block of 8

    // ---- Phase 0: load X tile [c][n], zero-pad cols 220..255 ----
    {
        const float4* g = (const float4*)(src + (size_t)b * (C_ * N_));
        for (int i = tid; i < (C_ * N_) / 4; i += NTHREADS) {
            int c = i / 55, p = i - c * 55;
            *(float4*)(X + c * NP_ + p * 4) = g[i];
        }
        for (int i = tid; i < C_ * (NP_ - N_); i += NTHREADS) {
            int c = i / 36, col = N_ + (i - c * 36);
            X[c * NP_ + col] = 0.f;
        }
    }

    const unsigned xa0 = (unsigned)__cvta_generic_to_shared(X + ng * 8);

    #pragma unroll 1
    for (int br = 0; br < 2; ++br) {
        const float* W  = br ? W_t     : W_s;
        const float* aS = br ? a_src_t : a_src_s;
        const float* aD = br ? a_dst_t : a_dst_s;
        float* sArr = br ? sT : sS;
        float* dArr = br ? dT : dS;

        // load transposed W into smem
        for (int i = tid; i < H_ * C_; i += NTHREADS) {
            int h = i >> 7, c = i & 127;
            Wt[c * WSTR + h] = W[i];
        }
        __syncthreads();

        // ---- main GEMM: 8h x 8n tile per thread, packed f32x2 FMA ----
        ull acc[8][4];
        #pragma unroll
        for (int h = 0; h < 8; ++h)
            #pragma unroll
            for (int p = 0; p < 4; ++p) acc[h][p] = 0ULL;

        const float* wp = Wt + hg * 8;
        unsigned xa = xa0;

        #pragma unroll 2
        for (int k = 0; k < C_; ++k) {
            const float4 w0 = *(const float4*)(wp);
            const float4 w1 = *(const float4*)(wp + 4);
            wp += WSTR;
            ull x0, x1, x2, x3;
            asm volatile("ld.shared.v2.u64 {%0,%1},[%2];" : "=l"(x0), "=l"(x1) : "r"(xa));
            asm volatile("ld.shared.v2.u64 {%0,%1},[%2];" : "=l"(x2), "=l"(x3) : "r"(xa + 16));
            xa += NP_ * 4;
            ull s;
            s = splat2(w0.x); acc[0][0]=fma2(s,x0,acc[0][0]); acc[0][1]=fma2(s,x1,acc[0][1]); acc[0][2]=fma2(s,x2,acc[0][2]); acc[0][3]=fma2(s,x3,acc[0][3]);
            s = splat2(w0.y); acc[1][0]=fma2(s,x0,acc[1][0]); acc[1][1]=fma2(s,x1,acc[1][1]); acc[1][2]=fma2(s,x2,acc[1][2]); acc[1][3]=fma2(s,x3,acc[1][3]);
            s = splat2(w0.z); acc[2][0]=fma2(s,x0,acc[2][0]); acc[2][1]=fma2(s,x1,acc[2][1]); acc[2][2]=fma2(s,x2,acc[2][2]); acc[2][3]=fma2(s,x3,acc[2][3]);
            s = splat2(w0.w); acc[3][0]=fma2(s,x0,acc[3][0]); acc[3][1]=fma2(s,x1,acc[3][1]); acc[3][2]=fma2(s,x2,acc[3][2]); acc[3][3]=fma2(s,x3,acc[3][3]);
            s = splat2(w1.x); acc[4][0]=fma2(s,x0,acc[4][0]); acc[4][1]=fma2(s,x1,acc[4][1]); acc[4][2]=fma2(s,x2,acc[4][2]); acc[4][3]=fma2(s,x3,acc[4][3]);
            s = splat2(w1.y); acc[5][0]=fma2(s,x0,acc[5][0]); acc[5][1]=fma2(s,x1,acc[5][1]); acc[5][2]=fma2(s,x2,acc[5][2]); acc[5][3]=fma2(s,x3,acc[5][3]);
            s = splat2(w1.z); acc[6][0]=fma2(s,x0,acc[6][0]); acc[6][1]=fma2(s,x1,acc[6][1]); acc[6][2]=fma2(s,x2,acc[6][2]); acc[6][3]=fma2(s,x3,acc[6][3]);
            s = splat2(w1.w); acc[7][0]=fma2(s,x0,acc[7][0]); acc[7][1]=fma2(s,x1,acc[7][1]); acc[7][2]=fma2(s,x2,acc[7][2]); acc[7][3]=fma2(s,x3,acc[7][3]);
        }

        // ---- per-thread epilogue: leaky + a-weighted partial sums over 8 h ----
        float sp[8], dp[8];
        #pragma unroll
        for (int i = 0; i < 8; ++i) { sp[i] = 0.f; dp[i] = 0.f; }
        #pragma unroll
        for (int h = 0; h < 8; ++h) {
            const float as = aS[hg * 8 + h];
            const float ad = aD[hg * 8 + h];
            #pragma unroll
            for (int p = 0; p < 4; ++p) {
                const ull v = acc[h][p];
                float lo = __uint_as_float((unsigned)v);
                float hi = __uint_as_float((unsigned)(v >> 32));
                lo = lo >= 0.f ? lo : 0.2f * lo;
                hi = hi >= 0.f ? hi : 0.2f * hi;
                sp[2*p]   = fmaf(as, lo, sp[2*p]);
                sp[2*p+1] = fmaf(as, hi, sp[2*p+1]);
                dp[2*p]   = fmaf(ad, lo, dp[2*p]);
                dp[2*p+1] = fmaf(ad, hi, dp[2*p+1]);
            }
        }

        __syncthreads();   // everyone done reading Wt — safe to reuse as partial buffer
        float* Ps = Wt;            // [16][256]
        float* Pd = Wt + 16 * NP_; // [16][256]  (16896 >= 8192)
        *(float4*)(Ps + hg * NP_ + ng * 8)     = make_float4(sp[0], sp[1], sp[2], sp[3]);
        *(float4*)(Ps + hg * NP_ + ng * 8 + 4) = make_float4(sp[4], sp[5], sp[6], sp[7]);
        *(float4*)(Pd + hg * NP_ + ng * 8)     = make_float4(dp[0], dp[1], dp[2], dp[3]);
        *(float4*)(Pd + hg * NP_ + ng * 8 + 4) = make_float4(dp[4], dp[5], dp[6], dp[7]);
        __syncthreads();

        if (tid < NP_) {
            float a2 = 0.f;
            #pragma unroll
            for (int g2 = 0; g2 < 16; ++g2) a2 += Ps[g2 * NP_ + tid];
            sArr[tid] = a2;
        } else {
            const int n = tid - NP_;
            float a2 = 0.f;
            #pragma unroll
            for (int g2 = 0; g2 < 16; ++g2) a2 += Pd[g2 * NP_ + n];
            dArr[n] = a2;
        }
        __syncthreads();
    }

    // ---- Phase 3: softmax + bias + store ----
    if (tid < N_) {
        const int r = tid;
        const int t = r / J_;
        const int i = r - t * J_;
        const float si = sS[r];
        const float* drow = dS + t * J_;
        float mx = -INFINITY;
        #pragma unroll
        for (int j = 0; j < J_; ++j) mx = fmaxf(mx, si + drow[j]);
        float ev[J_]; float sum = 0.f;
        #pragma unroll
        for (int j = 0; j < J_; ++j) { ev[j] = expf(si + drow[j] - mx); sum += ev[j]; }
        const float inv = 1.f / sum;
        float* o = out + ((size_t)b * N_ + r) * J_;
        const float* bias = sa_bias + i * J_;
        #pragma unroll
        for (int j = 0; j < J_; ++j) o[j] = ev[j] * inv + bias[j];
    }

    if (tid < N_) {
        const int r  = tid;
        const int j  = r / T_;
        const int ti = r - j * T_;
        const float si = sT[ti * J_ + j];
        float mx = -INFINITY;
        #pragma unroll
        for (int tj = 0; tj < T_; ++tj) mx = fmaxf(mx, si + dT[tj * J_ + j]);
        float ev[T_]; float sum = 0.f;
        #pragma unroll
        for (int tj = 0; tj < T_; ++tj) { ev[tj] = expf(si + dT[tj * J_ + j] - mx); sum += ev[tj]; }
        const float inv = 1.f / sum;
        float* o = out + SA_TOTAL + ((size_t)b * N_ + r) * T_;
        const float* bias = ta_bias + ti * T_;
        #pragma unroll
        for (int tj = 0; tj < T_; ++tj) o[tj] = ev[tj] * inv + bias[tj];
    }

    // ---- tail: the 4 scalar zeros (and any padding) ----
    if (b == 0) {
        for (long long i = SA_TOTAL + TA_TOTAL + tid; i < out_size; i += NTHREADS)
            out[i] = 0.f;
    }
}

extern "C" void kernel_launch(void* const* d_in, const int* in_sizes, int n_in,
                              void* d_out, int out_size)
{
    const float* src     = (const float*)d_in[0];
    const float* W_s     = (const float*)d_in[1];
    const float* a_src_s = (const float*)d_in[2];
    const float* a_dst_s = (const float*)d_in[3];
    const float* W_t     = (const float*)d_in[4];
    const float* a_src_t = (const float*)d_in[5];
    const float* a_dst_t = (const float*)d_in[6];
    const float* sa_bias = (const float*)d_in[7];
    const float* ta_bias = (const float*)d_in[8];
    float* out = (float*)d_out;

    const int smem_bytes = (C_ * NP_ + C_ * WSTR + 4 * NP_) * sizeof(float); // 202,752

    cudaFuncSetAttribute(dms_st_attention_kernel,
                         cudaFuncAttributeMaxDynamicSharedMemorySize, smem_bytes);

    dms_st_attention_kernel<<<B_, NTHREADS, smem_bytes>>>(
        src, W_s, a_src_s, a_dst_s, W_t, a_src_t, a_dst_t,
        sa_bias, ta_bias, out, (long long)out_size);
}

// round 4
// speedup vs baseline: 2.0534x; 1.4449x over previous
#include <cuda_runtime.h>
#include <cuda_bf16.h>
#include <cstdint>
#include <math.h>

#define B_  4096
#define C_  128
#define T_  10
#define J_  22
#define N_  220
#define H_  128
#define NTHREADS 512
#define WS  136      // W smem row stride in bf16 (128 + 8 pad)
#define XS  264      // X smem row stride in bf16 (256 + 8 pad)

static const long long SA_TOTAL = (long long)B_ * T_ * J_ * J_;   // 19,824,640
static const long long TA_TOTAL = (long long)B_ * J_ * T_ * T_;   //  9,011,200

// smem byte offsets
#define OFF_XHI 0                    // 128 x 264 bf16 = 67584
#define OFF_XLO 67584                // 67584
#define OFF_WHI 135168               // 128 x 136 bf16 = 34816
#define OFF_WLO 169984               // 34816
#define OFF_SD  204800               // sS,dS,sT,dT : 4 x 256 f32 = 4096
#define SMEM_TOTAL 208896

__device__ __forceinline__ uint32_t smem_u32(const void* p) {
    uint32_t a;
    asm("{ .reg .u64 t; cvta.to.shared.u64 t, %1; cvt.u32.u64 %0, t; }" : "=r"(a) : "l"(p));
    return a;
}

__device__ __forceinline__ void bf16_split2(float x, float y, uint32_t& hp, uint32_t& lp) {
    __nv_bfloat16 hx = __float2bfloat16(x);
    __nv_bfloat16 hy = __float2bfloat16(y);
    __nv_bfloat16 lx = __float2bfloat16(x - __bfloat162float(hx));
    __nv_bfloat16 ly = __float2bfloat16(y - __bfloat162float(hy));
    __nv_bfloat162 Hh; Hh.x = hx; Hh.y = hy;
    __nv_bfloat162 Ll; Ll.x = lx; Ll.y = ly;
    hp = *reinterpret_cast<uint32_t*>(&Hh);
    lp = *reinterpret_cast<uint32_t*>(&Ll);
}

// convert W [128h][128c] fp32 -> smem bf16 hi/lo, row-major, stride WS
__device__ __forceinline__ void convW(const float* __restrict__ W, char* smc, int tid) {
    const float2* w2 = (const float2*)W;
    for (int i = tid; i < 8192; i += NTHREADS) {
        int h = i >> 6, c0 = (i & 63) * 2;
        float2 v = w2[i];
        uint32_t hp, lp;
        bf16_split2(v.x, v.y, hp, lp);
        int e = (h * WS + c0) * 2;
        *(uint32_t*)(smc + OFF_WHI + e) = hp;
        *(uint32_t*)(smc + OFF_WLO + e) = lp;
    }
}

// one branch: 3-pass split-bf16 GEMM (128h x 256n x 128c) + fused leaky/a-reduce
__device__ __forceinline__ void branch_compute(
    uint32_t sb, const float* __restrict__ aS, const float* __restrict__ aD,
    float* __restrict__ sArr, float* __restrict__ dArr,
    int mi, int nh, int lane)
{
    float acc[16][4];
    #pragma unroll
    for (int nt = 0; nt < 16; ++nt)
        #pragma unroll
        for (int p = 0; p < 4; ++p) acc[nt][p] = 0.f;

    const int t  = lane >> 3, r = lane & 7;
    const uint32_t aoff = (uint32_t)(((mi * 16 + (t & 1) * 8 + r) * WS + (t >> 1) * 8) * 2);
    const int brow = ((lane >> 3) & 1) * 8 + (lane & 7);
    const uint32_t boff = (uint32_t)((brow * XS + nh * 128) * 2);

    #pragma unroll 1
    for (int pass = 0; pass < 3; ++pass) {
        const uint32_t Ab = sb + (pass == 2 ? OFF_WLO : OFF_WHI) + aoff;
        const uint32_t Bb = sb + (pass == 1 ? OFF_XLO : OFF_XHI) + boff;
        #pragma unroll 1
        for (int kc = 0; kc < 8; ++kc) {
            uint32_t a0, a1, a2, a3;
            asm volatile("ldmatrix.sync.aligned.m8n8.x4.shared.b16 {%0,%1,%2,%3}, [%4];"
                         : "=r"(a0), "=r"(a1), "=r"(a2), "=r"(a3) : "r"(Ab + kc * 32));
            const uint32_t Bk = Bb + (uint32_t)(kc * 16 * XS * 2);
            #pragma unroll
            for (int nt = 0; nt < 16; ++nt) {
                uint32_t b0, b1;
                asm volatile("ldmatrix.sync.aligned.m8n8.x2.trans.shared.b16 {%0,%1}, [%2];"
                             : "=r"(b0), "=r"(b1) : "r"(Bk + nt * 16));
                asm volatile("mma.sync.aligned.m16n8k16.row.col.f32.bf16.bf16.f32 "
                             "{%0,%1,%2,%3},{%4,%5,%6,%7},{%8,%9},{%0,%1,%2,%3};"
                             : "+f"(acc[nt][0]), "+f"(acc[nt][1]), "+f"(acc[nt][2]), "+f"(acc[nt][3])
                             : "r"(a0), "r"(a1), "r"(a2), "r"(a3), "r"(b0), "r"(b1));
            }
        }
    }

    // epilogue: C layout m16n8 -> lane g=lane>>2 rows {g, g+8}, cols {2q, 2q+1}
    const int g = lane >> 2, q = lane & 3;
    const float as0 = aS[mi * 16 + g],     as8 = aS[mi * 16 + 8 + g];
    const float ad0 = aD[mi * 16 + g],     ad8 = aD[mi * 16 + 8 + g];

    #pragma unroll
    for (int nt = 0; nt < 16; ++nt) {
        float v0 = acc[nt][0], v1 = acc[nt][1], v2 = acc[nt][2], v3 = acc[nt][3];
        const float L0 = fmaxf(v0, 0.2f * v0);
        const float L1 = fmaxf(v1, 0.2f * v1);
        const float L2 = fmaxf(v2, 0.2f * v2);
        const float L3 = fmaxf(v3, 0.2f * v3);
        float ss0 = as0 * L0 + as8 * L2;
        float ss1 = as0 * L1 + as8 * L3;
        float dd0 = ad0 * L0 + ad8 * L2;
        float dd1 = ad0 * L1 + ad8 * L3;
        #pragma unroll
        for (int m = 4; m <= 16; m <<= 1) {
            ss0 += __shfl_xor_sync(0xffffffffu, ss0, m);
            ss1 += __shfl_xor_sync(0xffffffffu, ss1, m);
            dd0 += __shfl_xor_sync(0xffffffffu, dd0, m);
            dd1 += __shfl_xor_sync(0xffffffffu, dd1, m);
        }
        if (g == 0) {
            const int n0 = nh * 128 + nt * 8 + q * 2;
            atomicAdd(&sArr[n0],     ss0);
            atomicAdd(&sArr[n0 + 1], ss1);
            atomicAdd(&dArr[n0],     dd0);
            atomicAdd(&dArr[n0 + 1], dd1);
        }
    }
}

__global__ void __launch_bounds__(NTHREADS, 1)
dms_st_attention_kernel(
    const float* __restrict__ src,
    const float* __restrict__ W_s,
    const float* __restrict__ a_src_s,
    const float* __restrict__ a_dst_s,
    const float* __restrict__ W_t,
    const float* __restrict__ a_src_t,
    const float* __restrict__ a_dst_t,
    const float* __restrict__ sa_bias,
    const float* __restrict__ ta_bias,
    float* __restrict__ out,
    long long out_size)
{
    extern __shared__ char smc[];
    const uint32_t sb = smem_u32(smc);
    const int tid  = threadIdx.x;
    const int lane = tid & 31;
    const int wid  = tid >> 5;
    const int b    = blockIdx.x;
    const int mi   = wid & 7;
    const int nh   = wid >> 3;

    float* sS = (float*)(smc + OFF_SD);
    float* dS = sS + 256;
    float* sT = dS + 256;
    float* dT = sT + 256;

    // zero s/d accumulators (1024 floats)
    for (int i = tid; i < 1024; i += NTHREADS) sS[i] = 0.f;

    // X convert: src[b] [128c][220n] fp32 -> Xhi/Xlo bf16, stride XS; pad n=220..263 zero
    {
        const float2* s2 = (const float2*)(src + (size_t)b * (C_ * N_));
        for (int i = tid; i < 14080; i += NTHREADS) {
            int c = i / 110, n0 = (i - c * 110) * 2;
            float2 v = s2[i];
            uint32_t hp, lp;
            bf16_split2(v.x, v.y, hp, lp);
            int e = (c * XS + n0) * 2;
            *(uint32_t*)(smc + OFF_XHI + e) = hp;
            *(uint32_t*)(smc + OFF_XLO + e) = lp;
        }
        for (int i = tid; i < 2816; i += NTHREADS) {   // 128c x 22 u32-pairs (n 220..263)
            int c = i / 22, n0 = 220 + (i - c * 22) * 2;
            int e = (c * XS + n0) * 2;
            *(uint32_t*)(smc + OFF_XHI + e) = 0u;
            *(uint32_t*)(smc + OFF_XLO + e) = 0u;
        }
    }

    convW(W_s, smc, tid);
    __syncthreads();

    branch_compute(sb, a_src_s, a_dst_s, sS, dS, mi, nh, lane);
    __syncthreads();

    convW(W_t, smc, tid);
    __syncthreads();

    branch_compute(sb, a_src_t, a_dst_t, sT, dT, mi, nh, lane);
    __syncthreads();

    // ---- softmax + bias + store ----
    if (tid < N_) {
        const int r = tid;
        const int t = r / J_;
        const int i = r - t * J_;
        const float si = sS[r];
        const float* drow = dS + t * J_;
        float mx = -INFINITY;
        #pragma unroll
        for (int j = 0; j < J_; ++j) mx = fmaxf(mx, si + drow[j]);
        float ev[J_]; float sum = 0.f;
        #pragma unroll
        for (int j = 0; j < J_; ++j) { ev[j] = expf(si + drow[j] - mx); sum += ev[j]; }
        const float inv = 1.f / sum;
        float* o = out + ((size_t)b * N_ + r) * J_;
        const float* bias = sa_bias + i * J_;
        #pragma unroll
        for (int j = 0; j < J_; ++j) o[j] = ev[j] * inv + bias[j];
    }
    if (tid < N_) {
        const int r  = tid;
        const int j  = r / T_;
        const int ti = r - j * T_;
        const float si = sT[ti * J_ + j];
        float mx = -INFINITY;
        #pragma unroll
        for (int tj = 0; tj < T_; ++tj) mx = fmaxf(mx, si + dT[tj * J_ + j]);
        float ev[T_]; float sum = 0.f;
        #pragma unroll
        for (int tj = 0; tj < T_; ++tj) { ev[tj] = expf(si + dT[tj * J_ + j] - mx); sum += ev[tj]; }
        const float inv = 1.f / sum;
        float* o = out + SA_TOTAL + ((size_t)b * N_ + r) * T_;
        const float* bias = ta_bias + ti * T_;
        #pragma unroll
        for (int tj = 0; tj < T_; ++tj) o[tj] = ev[tj] * inv + bias[tj];
    }
    if (b == 0) {
        for (long long i = SA_TOTAL + TA_TOTAL + tid; i < out_size; i += NTHREADS)
            out[i] = 0.f;
    }
}

extern "C" void kernel_launch(void* const* d_in, const int* in_sizes, int n_in,
                              void* d_out, int out_size)
{
    const float* src     = (const float*)d_in[0];
    const float* W_s     = (const float*)d_in[1];
    const float* a_src_s = (const float*)d_in[2];
    const float* a_dst_s = (const float*)d_in[3];
    const float* W_t     = (const float*)d_in[4];
    const float* a_src_t = (const float*)d_in[5];
    const float* a_dst_t = (const float*)d_in[6];
    const float* sa_bias = (const float*)d_in[7];
    const float* ta_bias = (const float*)d_in[8];
    float* out = (float*)d_out;

    cudaFuncSetAttribute(dms_st_attention_kernel,
                         cudaFuncAttributeMaxDynamicSharedMemorySize, SMEM_TOTAL);

    dms_st_attention_kernel<<<B_, NTHREADS, SMEM_TOTAL>>>(
        src, W_s, a_src_s, a_dst_s, W_t, a_src_t, a_dst_t,
        sa_bias, ta_bias, out, (long long)out_size);
}

// round 5
// speedup vs baseline: 2.3819x; 1.1600x over previous
#include <cuda_runtime.h>
#include <cuda_bf16.h>
#include <cstdint>
#include <math.h>

#define B_  4096
#define C_  128
#define T_  10
#define J_  22
#define N_  220
#define H_  128
#define NTHREADS 512
#define WS  136      // W smem row stride in bf16 (128 + 8 pad)
#define XS  264      // X smem row stride in bf16 (256 + 8 pad)

static const long long SA_TOTAL = (long long)B_ * T_ * J_ * J_;   // 19,824,640
static const long long TA_TOTAL = (long long)B_ * J_ * T_ * T_;   //  9,011,200

// smem byte offsets
#define OFF_XHI 0                    // 128 x 264 bf16 = 67584
#define OFF_XLO 67584                // 67584
#define OFF_WHI 135168               // 128 x 136 bf16 = 34816
#define OFF_WLO 169984               // 34816
#define OFF_SD  204800               // sS,dS,sT,dT : 4 x 256 f32 = 4096
#define SMEM_TOTAL 208896

__device__ __forceinline__ uint32_t smem_u32(const void* p) {
    uint32_t a;
    asm("{ .reg .u64 t; cvta.to.shared.u64 t, %1; cvt.u32.u64 %0, t; }" : "=r"(a) : "l"(p));
    return a;
}

__device__ __forceinline__ void bf16_split2(float x, float y, uint32_t& hp, uint32_t& lp) {
    __nv_bfloat16 hx = __float2bfloat16(x);
    __nv_bfloat16 hy = __float2bfloat16(y);
    __nv_bfloat16 lx = __float2bfloat16(x - __bfloat162float(hx));
    __nv_bfloat16 ly = __float2bfloat16(y - __bfloat162float(hy));
    __nv_bfloat162 Hh; Hh.x = hx; Hh.y = hy;
    __nv_bfloat162 Ll; Ll.x = lx; Ll.y = ly;
    hp = *reinterpret_cast<uint32_t*>(&Hh);
    lp = *reinterpret_cast<uint32_t*>(&Ll);
}

// convert W [128h][128c] fp32 -> smem bf16 hi/lo, row-major, stride WS
__device__ __forceinline__ void convW(const float* __restrict__ W, char* smc, int tid) {
    const float2* w2 = (const float2*)W;
    for (int i = tid; i < 8192; i += NTHREADS) {
        int h = i >> 6, c0 = (i & 63) * 2;
        float2 v = w2[i];
        uint32_t hp, lp;
        bf16_split2(v.x, v.y, hp, lp);
        int e = (h * WS + c0) * 2;
        *(uint32_t*)(smc + OFF_WHI + e) = hp;
        *(uint32_t*)(smc + OFF_WLO + e) = lp;
    }
}

#define LDSM_X4(r0,r1,r2,r3,addr) \
    asm volatile("ldmatrix.sync.aligned.m8n8.x4.shared.b16 {%0,%1,%2,%3}, [%4];" \
                 : "=r"(r0), "=r"(r1), "=r"(r2), "=r"(r3) : "r"(addr))
#define LDSM_X2T(r0,r1,addr) \
    asm volatile("ldmatrix.sync.aligned.m8n8.x2.trans.shared.b16 {%0,%1}, [%2];" \
                 : "=r"(r0), "=r"(r1) : "r"(addr))
#define MMA16816(acc,a0,a1,a2,a3,b0,b1) \
    asm volatile("mma.sync.aligned.m16n8k16.row.col.f32.bf16.bf16.f32 " \
                 "{%0,%1,%2,%3},{%4,%5,%6,%7},{%8,%9},{%0,%1,%2,%3};" \
                 : "+f"((acc)[0]), "+f"((acc)[1]), "+f"((acc)[2]), "+f"((acc)[3]) \
                 : "r"(a0), "r"(a1), "r"(a2), "r"(a3), "r"(b0), "r"(b1))

// one branch: 3-pass split-bf16 GEMM (128h x 256n x 128c) + fused leaky/a-reduce
// warp grid: mw = wid&3 (32 h rows = 2 m16 tiles), nw = wid>>2 (64 n cols = 8 n8 tiles)
__device__ __forceinline__ void branch_compute(
    uint32_t sb, const float* __restrict__ aS, const float* __restrict__ aD,
    float* __restrict__ sArr, float* __restrict__ dArr,
    int mw, int nw, int lane)
{
    float acc[2][8][4];
    #pragma unroll
    for (int mt = 0; mt < 2; ++mt)
        #pragma unroll
        for (int nt = 0; nt < 8; ++nt)
            #pragma unroll
            for (int p = 0; p < 4; ++p) acc[mt][nt][p] = 0.f;

    const int t = lane >> 3, r = lane & 7;
    // A tile base for mt: row = mw*32 + mt*16 + (t&1)*8 + r, col = (t>>1)*8
    const uint32_t aoff0 = (uint32_t)(((mw * 32 + (t & 1) * 8 + r) * WS + (t >> 1) * 8) * 2);
    const uint32_t aoff1 = aoff0 + (uint32_t)(16 * WS * 2);
    // B: rows k (trans), cols n ; lanes 0-7 rows 0-7, lanes 8-15 rows 8-15
    const int brow = ((lane >> 3) & 1) * 8 + (lane & 7);
    const uint32_t boff = (uint32_t)((brow * XS + nw * 64) * 2);

    const uint32_t AH = sb + OFF_WHI, AL = sb + OFF_WLO;
    const uint32_t BH = sb + OFF_XHI + boff, BL = sb + OFF_XLO + boff;

    #pragma unroll 1
    for (int kc = 0; kc < 8; ++kc) {
        uint32_t ah0[4], ah1[4], al0[4], al1[4];
        const uint32_t ka = (uint32_t)(kc * 32);
        LDSM_X4(ah0[0], ah0[1], ah0[2], ah0[3], AH + aoff0 + ka);
        LDSM_X4(ah1[0], ah1[1], ah1[2], ah1[3], AH + aoff1 + ka);
        LDSM_X4(al0[0], al0[1], al0[2], al0[3], AL + aoff0 + ka);
        LDSM_X4(al1[0], al1[1], al1[2], al1[3], AL + aoff1 + ka);
        const uint32_t kb = (uint32_t)(kc * 16 * XS * 2);
        #pragma unroll
        for (int nt = 0; nt < 8; ++nt) {
            uint32_t bh0, bh1, bl0, bl1;
            LDSM_X2T(bh0, bh1, BH + kb + nt * 16);
            LDSM_X2T(bl0, bl1, BL + kb + nt * 16);
            MMA16816(acc[0][nt], ah0[0], ah0[1], ah0[2], ah0[3], bh0, bh1);
            MMA16816(acc[1][nt], ah1[0], ah1[1], ah1[2], ah1[3], bh0, bh1);
            MMA16816(acc[0][nt], al0[0], al0[1], al0[2], al0[3], bh0, bh1);
            MMA16816(acc[1][nt], al1[0], al1[1], al1[2], al1[3], bh0, bh1);
            MMA16816(acc[0][nt], ah0[0], ah0[1], ah0[2], ah0[3], bl0, bl1);
            MMA16816(acc[1][nt], ah1[0], ah1[1], ah1[2], ah1[3], bl0, bl1);
        }
    }

    // epilogue: C m16n8: lane g=lane>>2 -> rows {g, g+8}, cols {2q, 2q+1}
    const int g = lane >> 2, q = lane & 3;
    const float as00 = aS[mw * 32 + g],      as08 = aS[mw * 32 + 8 + g];
    const float as10 = aS[mw * 32 + 16 + g], as18 = aS[mw * 32 + 24 + g];
    const float ad00 = aD[mw * 32 + g],      ad08 = aD[mw * 32 + 8 + g];
    const float ad10 = aD[mw * 32 + 16 + g], ad18 = aD[mw * 32 + 24 + g];

    #pragma unroll
    for (int nt = 0; nt < 8; ++nt) {
        float L00, L01, L02, L03, L10, L11, L12, L13, v;
        v = acc[0][nt][0]; L00 = fmaxf(v, 0.2f * v);
        v = acc[0][nt][1]; L01 = fmaxf(v, 0.2f * v);
        v = acc[0][nt][2]; L02 = fmaxf(v, 0.2f * v);
        v = acc[0][nt][3]; L03 = fmaxf(v, 0.2f * v);
        v = acc[1][nt][0]; L10 = fmaxf(v, 0.2f * v);
        v = acc[1][nt][1]; L11 = fmaxf(v, 0.2f * v);
        v = acc[1][nt][2]; L12 = fmaxf(v, 0.2f * v);
        v = acc[1][nt][3]; L13 = fmaxf(v, 0.2f * v);
        float ss0 = as00 * L00 + as08 * L02 + as10 * L10 + as18 * L12;
        float ss1 = as00 * L01 + as08 * L03 + as10 * L11 + as18 * L13;
        float dd0 = ad00 * L00 + ad08 * L02 + ad10 * L10 + ad18 * L12;
        float dd1 = ad00 * L01 + ad08 * L03 + ad10 * L11 + ad18 * L13;
        #pragma unroll
        for (int m = 4; m <= 16; m <<= 1) {
            ss0 += __shfl_xor_sync(0xffffffffu, ss0, m);
            ss1 += __shfl_xor_sync(0xffffffffu, ss1, m);
            dd0 += __shfl_xor_sync(0xffffffffu, dd0, m);
            dd1 += __shfl_xor_sync(0xffffffffu, dd1, m);
        }
        if (g == 0) {
            const int n0 = nw * 64 + nt * 8 + q * 2;
            atomicAdd(&sArr[n0],     ss0);
            atomicAdd(&sArr[n0 + 1], ss1);
            atomicAdd(&dArr[n0],     dd0);
            atomicAdd(&dArr[n0 + 1], dd1);
        }
    }
}

__global__ void __launch_bounds__(NTHREADS, 1)
dms_st_attention_kernel(
    const float* __restrict__ src,
    const float* __restrict__ W_s,
    const float* __restrict__ a_src_s,
    const float* __restrict__ a_dst_s,
    const float* __restrict__ W_t,
    const float* __restrict__ a_src_t,
    const float* __restrict__ a_dst_t,
    const float* __restrict__ sa_bias,
    const float* __restrict__ ta_bias,
    float* __restrict__ out,
    long long out_size)
{
    extern __shared__ char smc[];
    const uint32_t sb = smem_u32(smc);
    const int tid  = threadIdx.x;
    const int lane = tid & 31;
    const int wid  = tid >> 5;
    const int b    = blockIdx.x;
    const int mw   = wid & 3;
    const int nw   = wid >> 2;

    float* sS = (float*)(smc + OFF_SD);
    float* dS = sS + 256;
    float* sT = dS + 256;
    float* dT = sT + 256;

    for (int i = tid; i < 1024; i += NTHREADS) sS[i] = 0.f;

    // X convert: src[b] [128c][220n] fp32 -> Xhi/Xlo bf16 (stride XS); pad n=220..263
    {
        const float2* s2 = (const float2*)(src + (size_t)b * (C_ * N_));
        for (int i = tid; i < 14080; i += NTHREADS) {
            int c = i / 110, n0 = (i - c * 110) * 2;
            float2 v = s2[i];
            uint32_t hp, lp;
            bf16_split2(v.x, v.y, hp, lp);
            int e = (c * XS + n0) * 2;
            *(uint32_t*)(smc + OFF_XHI + e) = hp;
            *(uint32_t*)(smc + OFF_XLO + e) = lp;
        }
        for (int i = tid; i < 2816; i += NTHREADS) {
            int c = i / 22, n0 = 220 + (i - c * 22) * 2;
            int e = (c * XS + n0) * 2;
            *(uint32_t*)(smc + OFF_XHI + e) = 0u;
            *(uint32_t*)(smc + OFF_XLO + e) = 0u;
        }
    }

    convW(W_s, smc, tid);
    __syncthreads();

    branch_compute(sb, a_src_s, a_dst_s, sS, dS, mw, nw, lane);
    __syncthreads();

    convW(W_t, smc, tid);
    __syncthreads();

    branch_compute(sb, a_src_t, a_dst_t, sT, dT, mw, nw, lane);
    __syncthreads();

    // ---- softmax + bias + store ----
    if (tid < N_) {
        const int r = tid;
        const int t = r / J_;
        const int i = r - t * J_;
        const float si = sS[r];
        const float* drow = dS + t * J_;
        float mx = -INFINITY;
        #pragma unroll
        for (int j = 0; j < J_; ++j) mx = fmaxf(mx, si + drow[j]);
        float ev[J_]; float sum = 0.f;
        #pragma unroll
        for (int j = 0; j < J_; ++j) { ev[j] = expf(si + drow[j] - mx); sum += ev[j]; }
        const float inv = 1.f / sum;
        float* o = out + ((size_t)b * N_ + r) * J_;
        const float* bias = sa_bias + i * J_;
        #pragma unroll
        for (int j = 0; j < J_; ++j) o[j] = ev[j] * inv + bias[j];
    }
    if (tid < N_) {
        const int r  = tid;
        const int j  = r / T_;
        const int ti = r - j * T_;
        const float si = sT[ti * J_ + j];
        float mx = -INFINITY;
        #pragma unroll
        for (int tj = 0; tj < T_; ++tj) mx = fmaxf(mx, si + dT[tj * J_ + j]);
        float ev[T_]; float sum = 0.f;
        #pragma unroll
        for (int tj = 0; tj < T_; ++tj) { ev[tj] = expf(si + dT[tj * J_ + j] - mx); sum += ev[tj]; }
        const float inv = 1.f / sum;
        float* o = out + SA_TOTAL + ((size_t)b * N_ + r) * T_;
        const float* bias = ta_bias + ti * T_;
        #pragma unroll
        for (int tj = 0; tj < T_; ++tj) o[tj] = ev[tj] * inv + bias[tj];
    }
    if (b == 0) {
        for (long long i = SA_TOTAL + TA_TOTAL + tid; i < out_size; i += NTHREADS)
            out[i] = 0.f;
    }
}

extern "C" void kernel_launch(void* const* d_in, const int* in_sizes, int n_in,
                              void* d_out, int out_size)
{
    const float* src     = (const float*)d_in[0];
    const float* W_s     = (const float*)d_in[1];
    const float* a_src_s = (const float*)d_in[2];
    const float* a_dst_s = (const float*)d_in[3];
    const float* W_t     = (const float*)d_in[4];
    const float* a_src_t = (const float*)d_in[5];
    const float* a_dst_t = (const float*)d_in[6];
    const float* sa_bias = (const float*)d_in[7];
    const float* ta_bias = (const float*)d_in[8];
    float* out = (float*)d_out;

    cudaFuncSetAttribute(dms_st_attention_kernel,
                         cudaFuncAttributeMaxDynamicSharedMemorySize, SMEM_TOTAL);

    dms_st_attention_kernel<<<B_, NTHREADS, SMEM_TOTAL>>>(
        src, W_s, a_src_s, a_dst_s, W_t, a_src_t, a_dst_t,
        sa_bias, ta_bias, out, (long long)out_size);
}

// round 6
// speedup vs baseline: 2.9352x; 1.2323x over previous
#include <cuda_runtime.h>
#include <cuda_bf16.h>
#include <cstdint>
#include <math.h>

#define B_  4096
#define C_  128
#define T_  10
#define J_  22
#define N_  220
#define H_  128
#define NTHREADS 512
#define WS  136      // W smem row stride in bf16 (128 + 8 pad)
#define XS  264      // X smem row stride in bf16 (256 + 8 pad)

static const long long SA_TOTAL = (long long)B_ * T_ * J_ * J_;   // 19,824,640
static const long long TA_TOTAL = (long long)B_ * J_ * T_ * T_;   //  9,011,200

// smem byte offsets
#define OFF_XHI 0                    // 128 x 264 bf16 = 67584
#define OFF_XLO 67584                // 67584
#define OFF_WHI 135168               // 128 x 136 bf16 = 34816 (hi), lo contiguous
#define OFF_WLO 169984               // = OFF_WHI + 34816
#define OFF_SD  204800               // sS,dS,sT,dT : 4 x 256 f32 = 4096
#define SMEM_TOTAL 208896

#define WBYTES 69632                 // hi+lo per branch

// pre-converted W images (hi at 0, lo at 34816), one per branch
__device__ __align__(16) unsigned char g_Wbuf[2][WBYTES];

__device__ __forceinline__ uint32_t smem_u32(const void* p) {
    uint32_t a;
    asm("{ .reg .u64 t; cvta.to.shared.u64 t, %1; cvt.u32.u64 %0, t; }" : "=r"(a) : "l"(p));
    return a;
}

__device__ __forceinline__ void bf16_split2(float x, float y, uint32_t& hp, uint32_t& lp) {
    __nv_bfloat16 hx = __float2bfloat16(x);
    __nv_bfloat16 hy = __float2bfloat16(y);
    __nv_bfloat16 lx = __float2bfloat16(x - __bfloat162float(hx));
    __nv_bfloat16 ly = __float2bfloat16(y - __bfloat162float(hy));
    __nv_bfloat162 Hh; Hh.x = hx; Hh.y = hy;
    __nv_bfloat162 Ll; Ll.x = lx; Ll.y = ly;
    hp = *reinterpret_cast<uint32_t*>(&Hh);
    lp = *reinterpret_cast<uint32_t*>(&Ll);
}

// setup: convert W_s/W_t [128h][128c] fp32 -> padded bf16 hi/lo global images
__global__ void __launch_bounds__(512, 1)
setup_w_kernel(const float* __restrict__ W_s, const float* __restrict__ W_t)
{
    const int tg = blockIdx.x * 512 + threadIdx.x;   // 0..16383
    const int br = tg >> 13;
    const int i  = tg & 8191;
    const float2 v = ((const float2*)(br ? W_t : W_s))[i];
    const int h = i >> 6, c0 = (i & 63) * 2;
    uint32_t hp, lp;
    bf16_split2(v.x, v.y, hp, lp);
    const int e = (h * WS + c0) * 2;
    *(uint32_t*)(g_Wbuf[br] + e)         = hp;
    *(uint32_t*)(g_Wbuf[br] + 34816 + e) = lp;
}

#define LDSM_X4(r0,r1,r2,r3,addr) \
    asm volatile("ldmatrix.sync.aligned.m8n8.x4.shared.b16 {%0,%1,%2,%3}, [%4];" \
                 : "=r"(r0), "=r"(r1), "=r"(r2), "=r"(r3) : "r"(addr))
#define LDSM_X2T(r0,r1,addr) \
    asm volatile("ldmatrix.sync.aligned.m8n8.x2.trans.shared.b16 {%0,%1}, [%2];" \
                 : "=r"(r0), "=r"(r1) : "r"(addr))
#define MMA16816(acc,a0,a1,a2,a3,b0,b1) \
    asm volatile("mma.sync.aligned.m16n8k16.row.col.f32.bf16.bf16.f32 " \
                 "{%0,%1,%2,%3},{%4,%5,%6,%7},{%8,%9},{%0,%1,%2,%3};" \
                 : "+f"((acc)[0]), "+f"((acc)[1]), "+f"((acc)[2]), "+f"((acc)[3]) \
                 : "r"(a0), "r"(a1), "r"(a2), "r"(a3), "r"(b0), "r"(b1))

// 3-pass split-bf16 GEMM mainloop (128h x 256n x 128c), acc in caller regs
__device__ __forceinline__ void mainloop(
    uint32_t sb, int mw, int nw, int lane, float acc[2][8][4])
{
    #pragma unroll
    for (int mt = 0; mt < 2; ++mt)
        #pragma unroll
        for (int nt = 0; nt < 8; ++nt)
            #pragma unroll
            for (int p = 0; p < 4; ++p) acc[mt][nt][p] = 0.f;

    const int t = lane >> 3, r = lane & 7;
    const uint32_t aoff0 = (uint32_t)(((mw * 32 + (t & 1) * 8 + r) * WS + (t >> 1) * 8) * 2);
    const uint32_t aoff1 = aoff0 + (uint32_t)(16 * WS * 2);
    const int brow = ((lane >> 3) & 1) * 8 + (lane & 7);
    const uint32_t boff = (uint32_t)((brow * XS + nw * 64) * 2);

    const uint32_t AH = sb + OFF_WHI, AL = sb + OFF_WLO;
    const uint32_t BH = sb + OFF_XHI + boff, BL = sb + OFF_XLO + boff;

    #pragma unroll 1
    for (int kc = 0; kc < 8; ++kc) {
        uint32_t ah0[4], ah1[4], al0[4], al1[4];
        const uint32_t ka = (uint32_t)(kc * 32);
        LDSM_X4(ah0[0], ah0[1], ah0[2], ah0[3], AH + aoff0 + ka);
        LDSM_X4(ah1[0], ah1[1], ah1[2], ah1[3], AH + aoff1 + ka);
        LDSM_X4(al0[0], al0[1], al0[2], al0[3], AL + aoff0 + ka);
        LDSM_X4(al1[0], al1[1], al1[2], al1[3], AL + aoff1 + ka);
        const uint32_t kb = (uint32_t)(kc * 16 * XS * 2);

        uint32_t bh[2][2], bl[2][2];
        LDSM_X2T(bh[0][0], bh[0][1], BH + kb);
        LDSM_X2T(bl[0][0], bl[0][1], BL + kb);
        #pragma unroll
        for (int nt = 0; nt < 8; ++nt) {
            const int cur = nt & 1, nxt = cur ^ 1;
            if (nt < 7) {
                LDSM_X2T(bh[nxt][0], bh[nxt][1], BH + kb + (nt + 1) * 16);
                LDSM_X2T(bl[nxt][0], bl[nxt][1], BL + kb + (nt + 1) * 16);
            }
            MMA16816(acc[0][nt], ah0[0], ah0[1], ah0[2], ah0[3], bh[cur][0], bh[cur][1]);
            MMA16816(acc[1][nt], ah1[0], ah1[1], ah1[2], ah1[3], bh[cur][0], bh[cur][1]);
            MMA16816(acc[0][nt], al0[0], al0[1], al0[2], al0[3], bh[cur][0], bh[cur][1]);
            MMA16816(acc[1][nt], al1[0], al1[1], al1[2], al1[3], bh[cur][0], bh[cur][1]);
            MMA16816(acc[0][nt], ah0[0], ah0[1], ah0[2], ah0[3], bl[cur][0], bl[cur][1]);
            MMA16816(acc[1][nt], ah1[0], ah1[1], ah1[2], ah1[3], bl[cur][0], bl[cur][1]);
        }
    }
}

// leaky + a-weighted reduce + shfl tree + spread smem atomics
__device__ __forceinline__ void epilogue(
    float acc[2][8][4], const float* __restrict__ aS, const float* __restrict__ aD,
    float* __restrict__ sArr, float* __restrict__ dArr, int mw, int nw, int lane)
{
    const int g = lane >> 2, q = lane & 3;
    const float as00 = aS[mw * 32 + g],      as08 = aS[mw * 32 + 8 + g];
    const float as10 = aS[mw * 32 + 16 + g], as18 = aS[mw * 32 + 24 + g];
    const float ad00 = aD[mw * 32 + g],      ad08 = aD[mw * 32 + 8 + g];
    const float ad10 = aD[mw * 32 + 16 + g], ad18 = aD[mw * 32 + 24 + g];

    #pragma unroll
    for (int nt = 0; nt < 8; ++nt) {
        float L00, L01, L02, L03, L10, L11, L12, L13, v;
        v = acc[0][nt][0]; L00 = fmaxf(v, 0.2f * v);
        v = acc[0][nt][1]; L01 = fmaxf(v, 0.2f * v);
        v = acc[0][nt][2]; L02 = fmaxf(v, 0.2f * v);
        v = acc[0][nt][3]; L03 = fmaxf(v, 0.2f * v);
        v = acc[1][nt][0]; L10 = fmaxf(v, 0.2f * v);
        v = acc[1][nt][1]; L11 = fmaxf(v, 0.2f * v);
        v = acc[1][nt][2]; L12 = fmaxf(v, 0.2f * v);
        v = acc[1][nt][3]; L13 = fmaxf(v, 0.2f * v);
        float ss0 = as00 * L00 + as08 * L02 + as10 * L10 + as18 * L12;
        float ss1 = as00 * L01 + as08 * L03 + as10 * L11 + as18 * L13;
        float dd0 = ad00 * L00 + ad08 * L02 + ad10 * L10 + ad18 * L12;
        float dd1 = ad00 * L01 + ad08 * L03 + ad10 * L11 + ad18 * L13;
        #pragma unroll
        for (int m = 4; m <= 16; m <<= 1) {
            ss0 += __shfl_xor_sync(0xffffffffu, ss0, m);
            ss1 += __shfl_xor_sync(0xffffffffu, ss1, m);
            dd0 += __shfl_xor_sync(0xffffffffu, dd0, m);
            dd1 += __shfl_xor_sync(0xffffffffu, dd1, m);
        }
        if (g == 0) {
            const int n0 = nw * 64 + nt * 8 + q * 2;
            atomicAdd(&sArr[n0],     ss0);
            atomicAdd(&sArr[n0 + 1], ss1);
            atomicAdd(&dArr[n0],     dd0);
            atomicAdd(&dArr[n0 + 1], dd1);
        }
    }
}

__device__ __forceinline__ void copyW(char* smc, int br, int tid) {
    const uint4* g4 = (const uint4*)g_Wbuf[br];
    uint4* s4 = (uint4*)(smc + OFF_WHI);
    #pragma unroll
    for (int u = 0; u < 8; ++u) s4[tid + u * 512] = g4[tid + u * 512];
    if (tid < 256) s4[4096 + tid] = g4[4096 + tid];
}

__global__ void __launch_bounds__(NTHREADS, 1)
dms_st_attention_kernel(
    const float* __restrict__ src,
    const float* __restrict__ a_src_s,
    const float* __restrict__ a_dst_s,
    const float* __restrict__ a_src_t,
    const float* __restrict__ a_dst_t,
    const float* __restrict__ sa_bias,
    const float* __restrict__ ta_bias,
    float* __restrict__ out,
    long long out_size)
{
    extern __shared__ char smc[];
    const uint32_t sb = smem_u32(smc);
    const int tid  = threadIdx.x;
    const int lane = tid & 31;
    const int wid  = tid >> 5;
    const int b    = blockIdx.x;
    const int mw   = wid & 3;
    const int nw   = wid >> 2;

    float* sS = (float*)(smc + OFF_SD);
    float* dS = sS + 256;
    float* sT = dS + 256;
    float* dT = sT + 256;

    sS[tid] = 0.f; sS[tid + 512] = 0.f;   // zero sS,dS,sT,dT (1024 floats)

    // ---- X convert: src[b] [128c][220n] fp32 -> Xhi/Xlo bf16 (stride XS) ----
    {
        const float4* g = (const float4*)(src + (size_t)b * (C_ * N_));  // 7040 float4
        #pragma unroll
        for (int u = 0; u < 14; ++u) {
            const int idx = u * 512 + tid;
            if (u == 13 && idx >= 7040) break;
            const int c = idx / 55, p = idx - c * 55, n0 = p * 4;
            const float4 v = g[idx];
            uint32_t hp0, lp0, hp1, lp1;
            bf16_split2(v.x, v.y, hp0, lp0);
            bf16_split2(v.z, v.w, hp1, lp1);
            const int e = (c * XS + n0) * 2;
            *(uint2*)(smc + OFF_XHI + e) = make_uint2(hp0, hp1);
            *(uint2*)(smc + OFF_XLO + e) = make_uint2(lp0, lp1);
        }
        // zero pad cols 220..263
        #pragma unroll
        for (int u = 0; u < 6; ++u) {
            const int i = u * 512 + tid;
            if (i >= 2816) break;
            const int c = i / 22, n0 = 220 + (i - c * 22) * 2;
            const int e = (c * XS + n0) * 2;
            *(uint32_t*)(smc + OFF_XHI + e) = 0u;
            *(uint32_t*)(smc + OFF_XLO + e) = 0u;
        }
    }

    copyW(smc, 0, tid);
    __syncthreads();

    float acc[2][8][4];

    // ---- branch S ----
    mainloop(sb, mw, nw, lane, acc);
    __syncthreads();
    copyW(smc, 1, tid);                       // W_t copy: loads/stores overlap epilogue latency
    epilogue(acc, a_src_s, a_dst_s, sS, dS, mw, nw, lane);
    __syncthreads();

    // ---- branch T ----
    mainloop(sb, mw, nw, lane, acc);
    epilogue(acc, a_src_t, a_dst_t, sT, dT, mw, nw, lane);
    __syncthreads();

    // ---- softmax + bias + store ----
    if (tid < N_) {
        const int r = tid;
        const int t = r / J_;
        const int i = r - t * J_;
        const float si = sS[r];
        const float* drow = dS + t * J_;
        float mx = -INFINITY;
        #pragma unroll
        for (int j = 0; j < J_; ++j) mx = fmaxf(mx, si + drow[j]);
        float ev[J_]; float sum = 0.f;
        #pragma unroll
        for (int j = 0; j < J_; ++j) { ev[j] = __expf(si + drow[j] - mx); sum += ev[j]; }
        const float inv = __fdividef(1.f, sum);
        float* o = out + ((size_t)b * N_ + r) * J_;
        const float* bias = sa_bias + i * J_;
        #pragma unroll
        for (int j = 0; j < J_; ++j) o[j] = ev[j] * inv + bias[j];
    }
    if (tid < N_) {
        const int r  = tid;
        const int j  = r / T_;
        const int ti = r - j * T_;
        const float si = sT[ti * J_ + j];
        float mx = -INFINITY;
        #pragma unroll
        for (int tj = 0; tj < T_; ++tj) mx = fmaxf(mx, si + dT[tj * J_ + j]);
        float ev[T_]; float sum = 0.f;
        #pragma unroll
        for (int tj = 0; tj < T_; ++tj) { ev[tj] = __expf(si + dT[tj * J_ + j] - mx); sum += ev[tj]; }
        const float inv = __fdividef(1.f, sum);
        float* o = out + SA_TOTAL + ((size_t)b * N_ + r) * T_;
        const float* bias = ta_bias + ti * T_;
        #pragma unroll
        for (int tj = 0; tj < T_; ++tj) o[tj] = ev[tj] * inv + bias[tj];
    }
    if (b == 0) {
        for (long long i = SA_TOTAL + TA_TOTAL + tid; i < out_size; i += NTHREADS)
            out[i] = 0.f;
    }
}

extern "C" void kernel_launch(void* const* d_in, const int* in_sizes, int n_in,
                              void* d_out, int out_size)
{
    const float* src     = (const float*)d_in[0];
    const float* W_s     = (const float*)d_in[1];
    const float* a_src_s = (const float*)d_in[2];
    const float* a_dst_s = (const float*)d_in[3];
    const float* W_t     = (const float*)d_in[4];
    const float* a_src_t = (const float*)d_in[5];
    const float* a_dst_t = (const float*)d_in[6];
    const float* sa_bias = (const float*)d_in[7];
    const float* ta_bias = (const float*)d_in[8];
    float* out = (float*)d_out;

    cudaFuncSetAttribute(dms_st_attention_kernel,
                         cudaFuncAttributeMaxDynamicSharedMemorySize, SMEM_TOTAL);

    setup_w_kernel<<<32, 512>>>(W_s, W_t);
    dms_st_attention_kernel<<<B_, NTHREADS, SMEM_TOTAL>>>(
        src, a_src_s, a_dst_s, a_src_t, a_dst_t,
        sa_bias, ta_bias, out, (long long)out_size);
}

// round 7
// speedup vs baseline: 3.3501x; 1.1413x over previous
#include <cuda_runtime.h>
#include <cuda_bf16.h>
#include <cstdint>
#include <math.h>

#define B_  4096
#define C_  128
#define T_  10
#define J_  22
#define N_  220
#define H_  128
#define NTHREADS 512
#define WS  136      // W smem row stride in bf16 (128 + 8 pad)
#define XS  264      // X smem row stride in bf16 (256 + 8 pad)

static const long long SA_TOTAL = (long long)B_ * T_ * J_ * J_;   // 19,824,640
static const long long TA_TOTAL = (long long)B_ * J_ * T_ * T_;   //  9,011,200

// smem byte offsets
#define OFF_XHI 0                    // 128 x 264 bf16 = 67584 ; reused as output stage
#define OFF_XLO 67584
#define OFF_WHI 135168               // hi, lo contiguous (34816 each)
#define OFF_WLO 169984
#define OFF_SD  204800               // sS,dS,sT,dT : 4 x 256 f32 = 4096
#define SMEM_TOTAL 208896

#define WBYTES 69632

__device__ __align__(16) unsigned char g_Wbuf[2][WBYTES];

__device__ __forceinline__ uint32_t smem_u32(const void* p) {
    uint32_t a;
    asm("{ .reg .u64 t; cvta.to.shared.u64 t, %1; cvt.u32.u64 %0, t; }" : "=r"(a) : "l"(p));
    return a;
}

__device__ __forceinline__ void bf16_split2(float x, float y, uint32_t& hp, uint32_t& lp) {
    __nv_bfloat16 hx = __float2bfloat16(x);
    __nv_bfloat16 hy = __float2bfloat16(y);
    __nv_bfloat16 lx = __float2bfloat16(x - __bfloat162float(hx));
    __nv_bfloat16 ly = __float2bfloat16(y - __bfloat162float(hy));
    __nv_bfloat162 Hh; Hh.x = hx; Hh.y = hy;
    __nv_bfloat162 Ll; Ll.x = lx; Ll.y = ly;
    hp = *reinterpret_cast<uint32_t*>(&Hh);
    lp = *reinterpret_cast<uint32_t*>(&Ll);
}

__global__ void __launch_bounds__(512, 1)
setup_w_kernel(const float* __restrict__ W_s, const float* __restrict__ W_t)
{
    const int tg = blockIdx.x * 512 + threadIdx.x;
    const int br = tg >> 13;
    const int i  = tg & 8191;
    const float2 v = ((const float2*)(br ? W_t : W_s))[i];
    const int h = i >> 6, c0 = (i & 63) * 2;
    uint32_t hp, lp;
    bf16_split2(v.x, v.y, hp, lp);
    const int e = (h * WS + c0) * 2;
    *(uint32_t*)(g_Wbuf[br] + e)         = hp;
    *(uint32_t*)(g_Wbuf[br] + 34816 + e) = lp;
}

#define LDSM_X4(r0,r1,r2,r3,addr) \
    asm volatile("ldmatrix.sync.aligned.m8n8.x4.shared.b16 {%0,%1,%2,%3}, [%4];" \
                 : "=r"(r0), "=r"(r1), "=r"(r2), "=r"(r3) : "r"(addr))
#define LDSM_X2T(r0,r1,addr) \
    asm volatile("ldmatrix.sync.aligned.m8n8.x2.trans.shared.b16 {%0,%1}, [%2];" \
                 : "=r"(r0), "=r"(r1) : "r"(addr))
#define MMA16816(acc,a0,a1,a2,a3,b0,b1) \
    asm volatile("mma.sync.aligned.m16n8k16.row.col.f32.bf16.bf16.f32 " \
                 "{%0,%1,%2,%3},{%4,%5,%6,%7},{%8,%9},{%0,%1,%2,%3};" \
                 : "+f"((acc)[0]), "+f"((acc)[1]), "+f"((acc)[2]), "+f"((acc)[3]) \
                 : "r"(a0), "r"(a1), "r"(a2), "r"(a3), "r"(b0), "r"(b1))

__device__ __forceinline__ void mainloop(
    uint32_t sb, int mw, int nw, int lane, float acc[2][8][4])
{
    #pragma unroll
    for (int mt = 0; mt < 2; ++mt)
        #pragma unroll
        for (int nt = 0; nt < 8; ++nt)
            #pragma unroll
            for (int p = 0; p < 4; ++p) acc[mt][nt][p] = 0.f;

    const int t = lane >> 3, r = lane & 7;
    const uint32_t aoff0 = (uint32_t)(((mw * 32 + (t & 1) * 8 + r) * WS + (t >> 1) * 8) * 2);
    const uint32_t aoff1 = aoff0 + (uint32_t)(16 * WS * 2);
    const int brow = ((lane >> 3) & 1) * 8 + (lane & 7);
    const uint32_t boff = (uint32_t)((brow * XS + nw * 64) * 2);

    const uint32_t AH = sb + OFF_WHI, AL = sb + OFF_WLO;
    const uint32_t BH = sb + OFF_XHI + boff, BL = sb + OFF_XLO + boff;

    #pragma unroll 1
    for (int kc = 0; kc < 8; ++kc) {
        uint32_t ah0[4], ah1[4], al0[4], al1[4];
        const uint32_t ka = (uint32_t)(kc * 32);
        LDSM_X4(ah0[0], ah0[1], ah0[2], ah0[3], AH + aoff0 + ka);
        LDSM_X4(ah1[0], ah1[1], ah1[2], ah1[3], AH + aoff1 + ka);
        LDSM_X4(al0[0], al0[1], al0[2], al0[3], AL + aoff0 + ka);
        LDSM_X4(al1[0], al1[1], al1[2], al1[3], AL + aoff1 + ka);
        const uint32_t kb = (uint32_t)(kc * 16 * XS * 2);

        uint32_t bh[2][2], bl[2][2];
        LDSM_X2T(bh[0][0], bh[0][1], BH + kb);
        LDSM_X2T(bl[0][0], bl[0][1], BL + kb);
        #pragma unroll
        for (int nt = 0; nt < 8; ++nt) {
            const int cur = nt & 1, nxt = cur ^ 1;
            if (nt < 7) {
                LDSM_X2T(bh[nxt][0], bh[nxt][1], BH + kb + (nt + 1) * 16);
                LDSM_X2T(bl[nxt][0], bl[nxt][1], BL + kb + (nt + 1) * 16);
            }
            MMA16816(acc[0][nt], ah0[0], ah0[1], ah0[2], ah0[3], bh[cur][0], bh[cur][1]);
            MMA16816(acc[1][nt], ah1[0], ah1[1], ah1[2], ah1[3], bh[cur][0], bh[cur][1]);
            MMA16816(acc[0][nt], al0[0], al0[1], al0[2], al0[3], bh[cur][0], bh[cur][1]);
            MMA16816(acc[1][nt], al1[0], al1[1], al1[2], al1[3], bh[cur][0], bh[cur][1]);
            MMA16816(acc[0][nt], ah0[0], ah0[1], ah0[2], ah0[3], bl[cur][0], bl[cur][1]);
            MMA16816(acc[1][nt], ah1[0], ah1[1], ah1[2], ah1[3], bl[cur][0], bl[cur][1]);
        }
    }
}

__device__ __forceinline__ void epilogue(
    float acc[2][8][4], const float* __restrict__ aS, const float* __restrict__ aD,
    float* __restrict__ sArr, float* __restrict__ dArr, int mw, int nw, int lane)
{
    const int g = lane >> 2, q = lane & 3;
    const float as00 = aS[mw * 32 + g],      as08 = aS[mw * 32 + 8 + g];
    const float as10 = aS[mw * 32 + 16 + g], as18 = aS[mw * 32 + 24 + g];
    const float ad00 = aD[mw * 32 + g],      ad08 = aD[mw * 32 + 8 + g];
    const float ad10 = aD[mw * 32 + 16 + g], ad18 = aD[mw * 32 + 24 + g];

    #pragma unroll
    for (int nt = 0; nt < 8; ++nt) {
        float L00, L01, L02, L03, L10, L11, L12, L13, v;
        v = acc[0][nt][0]; L00 = fmaxf(v, 0.2f * v);
        v = acc[0][nt][1]; L01 = fmaxf(v, 0.2f * v);
        v = acc[0][nt][2]; L02 = fmaxf(v, 0.2f * v);
        v = acc[0][nt][3]; L03 = fmaxf(v, 0.2f * v);
        v = acc[1][nt][0]; L10 = fmaxf(v, 0.2f * v);
        v = acc[1][nt][1]; L11 = fmaxf(v, 0.2f * v);
        v = acc[1][nt][2]; L12 = fmaxf(v, 0.2f * v);
        v = acc[1][nt][3]; L13 = fmaxf(v, 0.2f * v);
        float ss0 = as00 * L00 + as08 * L02 + as10 * L10 + as18 * L12;
        float ss1 = as00 * L01 + as08 * L03 + as10 * L11 + as18 * L13;
        float dd0 = ad00 * L00 + ad08 * L02 + ad10 * L10 + ad18 * L12;
        float dd1 = ad00 * L01 + ad08 * L03 + ad10 * L11 + ad18 * L13;
        #pragma unroll
        for (int m = 4; m <= 16; m <<= 1) {
            ss0 += __shfl_xor_sync(0xffffffffu, ss0, m);
            ss1 += __shfl_xor_sync(0xffffffffu, ss1, m);
            dd0 += __shfl_xor_sync(0xffffffffu, dd0, m);
            dd1 += __shfl_xor_sync(0xffffffffu, dd1, m);
        }
        if (g == 0) {
            const int n0 = nw * 64 + nt * 8 + q * 2;
            atomicAdd(&sArr[n0],     ss0);
            atomicAdd(&sArr[n0 + 1], ss1);
            atomicAdd(&dArr[n0],     dd0);
            atomicAdd(&dArr[n0 + 1], dd1);
        }
    }
}

__device__ __forceinline__ void copyW(char* smc, int br, int tid) {
    const uint4* g4 = (const uint4*)g_Wbuf[br];
    uint4* s4 = (uint4*)(smc + OFF_WHI);
    #pragma unroll
    for (int u = 0; u < 8; ++u) s4[tid + u * 512] = g4[tid + u * 512];
    if (tid < 256) s4[4096 + tid] = g4[4096 + tid];
}

__global__ void __launch_bounds__(NTHREADS, 1)
dms_st_attention_kernel(
    const float* __restrict__ src,
    const float* __restrict__ a_src_s,
    const float* __restrict__ a_dst_s,
    const float* __restrict__ a_src_t,
    const float* __restrict__ a_dst_t,
    const float* __restrict__ sa_bias,
    const float* __restrict__ ta_bias,
    float* __restrict__ out,
    long long out_size)
{
    extern __shared__ char smc[];
    const uint32_t sb = smem_u32(smc);
    const int tid  = threadIdx.x;
    const int lane = tid & 31;
    const int wid  = tid >> 5;
    const int b    = blockIdx.x;
    const int mw   = wid & 3;
    const int nw   = wid >> 2;

    float* sS = (float*)(smc + OFF_SD);
    float* dS = sS + 256;
    float* sT = dS + 256;
    float* dT = sT + 256;

    sS[tid] = 0.f; sS[tid + 512] = 0.f;

    // ---- X convert ----
    {
        const float4* g = (const float4*)(src + (size_t)b * (C_ * N_));
        #pragma unroll
        for (int u = 0; u < 14; ++u) {
            const int idx = u * 512 + tid;
            if (u == 13 && idx >= 7040) break;
            const int c = idx / 55, p = idx - c * 55, n0 = p * 4;
            const float4 v = g[idx];
            uint32_t hp0, lp0, hp1, lp1;
            bf16_split2(v.x, v.y, hp0, lp0);
            bf16_split2(v.z, v.w, hp1, lp1);
            const int e = (c * XS + n0) * 2;
            *(uint2*)(smc + OFF_XHI + e) = make_uint2(hp0, hp1);
            *(uint2*)(smc + OFF_XLO + e) = make_uint2(lp0, lp1);
        }
        #pragma unroll
        for (int u = 0; u < 6; ++u) {
            const int i = u * 512 + tid;
            if (i >= 2816) break;
            const int c = i / 22, n0 = 220 + (i - c * 22) * 2;
            const int e = (c * XS + n0) * 2;
            *(uint32_t*)(smc + OFF_XHI + e) = 0u;
            *(uint32_t*)(smc + OFF_XLO + e) = 0u;
        }
    }

    copyW(smc, 0, tid);

    // L2 prefetch of next-wave CTA's src (hides DRAM latency for its X convert)
    if (b + 148 < B_) {
        const char* nsrc = (const char*)(src + (size_t)(b + 148) * (C_ * N_));
        #pragma unroll
        for (int u = 0; u < 2; ++u) {
            const int line = tid + u * 512;
            if (line < 880)
                asm volatile("prefetch.global.L2 [%0];" :: "l"(nsrc + line * 128));
        }
    }
    __syncthreads();

    float acc[2][8][4];

    // ---- branch S ----
    mainloop(sb, mw, nw, lane, acc);
    __syncthreads();
    copyW(smc, 1, tid);
    epilogue(acc, a_src_s, a_dst_s, sS, dS, mw, nw, lane);
    __syncthreads();

    // ---- branch T ----
    mainloop(sb, mw, nw, lane, acc);
    epilogue(acc, a_src_t, a_dst_t, sT, dT, mw, nw, lane);
    __syncthreads();

    // ---- softmax + bias -> smem stage (X area dead now) ----
    float* sa_stage = (float*)(smc + OFF_XHI);            // 4840 floats
    float* ta_stage = sa_stage + 4840;                    // 2200 floats

    if (tid < N_) {                                       // warps 0..6: spatial
        const int r = tid;
        const int t = r / J_;
        const int i = r - t * J_;
        const float si = sS[r];
        const float* drow = dS + t * J_;
        float mx = -INFINITY;
        #pragma unroll
        for (int j = 0; j < J_; ++j) mx = fmaxf(mx, si + drow[j]);
        float ev[J_]; float sum = 0.f;
        #pragma unroll
        for (int j = 0; j < J_; ++j) { ev[j] = __expf(si + drow[j] - mx); sum += ev[j]; }
        const float inv = __fdividef(1.f, sum);
        float* o = sa_stage + r * J_;
        const float* bias = sa_bias + i * J_;
        #pragma unroll
        for (int j = 0; j < J_; ++j) o[j] = ev[j] * inv + bias[j];
    } else if (tid >= 256 && tid < 256 + N_) {            // warps 8..14: temporal
        const int r  = tid - 256;
        const int j  = r / T_;
        const int ti = r - j * T_;
        const float si = sT[ti * J_ + j];
        float mx = -INFINITY;
        #pragma unroll
        for (int tj = 0; tj < T_; ++tj) mx = fmaxf(mx, si + dT[tj * J_ + j]);
        float ev[T_]; float sum = 0.f;
        #pragma unroll
        for (int tj = 0; tj < T_; ++tj) { ev[tj] = __expf(si + dT[tj * J_ + j] - mx); sum += ev[tj]; }
        const float inv = __fdividef(1.f, sum);
        float* o = ta_stage + r * T_;
        const float* bias = ta_bias + ti * T_;
        #pragma unroll
        for (int tj = 0; tj < T_; ++tj) o[tj] = ev[tj] * inv + bias[tj];
    }
    __syncthreads();

    // ---- coalesced copy-out: sa 1210 float4, ta 550 float4 ----
    {
        const float4* s4 = (const float4*)sa_stage;
        float4* o4 = (float4*)(out + (size_t)b * 4840);
        #pragma unroll
        for (int u = 0; u < 3; ++u) {
            const int i = u * 512 + tid;
            if (i < 1210) o4[i] = s4[i];
        }
        const float4* t4 = (const float4*)ta_stage;
        float4* p4 = (float4*)(out + SA_TOTAL + (size_t)b * 2200);
        #pragma unroll
        for (int u = 0; u < 2; ++u) {
            const int i = u * 512 + tid;
            if (i < 550) p4[i] = t4[i];
        }
    }

    if (b == 0) {
        for (long long i = SA_TOTAL + TA_TOTAL + tid; i < out_size; i += NTHREADS)
            out[i] = 0.f;
    }
}

extern "C" void kernel_launch(void* const* d_in, const int* in_sizes, int n_in,
                              void* d_out, int out_size)
{
    const float* src     = (const float*)d_in[0];
    const float* W_s     = (const float*)d_in[1];
    const float* a_src_s = (const float*)d_in[2];
    const float* a_dst_s = (const float*)d_in[3];
    const float* W_t     = (const float*)d_in[4];
    const float* a_src_t = (const float*)d_in[5];
    const float* a_dst_t = (const float*)d_in[6];
    const float* sa_bias = (const float*)d_in[7];
    const float* ta_bias = (const float*)d_in[8];
    float* out = (float*)d_out;

    cudaFuncSetAttribute(dms_st_attention_kernel,
                         cudaFuncAttributeMaxDynamicSharedMemorySize, SMEM_TOTAL);

    setup_w_kernel<<<32, 512>>>(W_s, W_t);
    dms_st_attention_kernel<<<B_, NTHREADS, SMEM_TOTAL>>>(
        src, a_src_s, a_dst_s, a_src_t, a_dst_t,
        sa_bias, ta_bias, out, (long long)out_size);
}

// round 8
// speedup vs baseline: 3.9416x; 1.1766x over previous
#include <cuda_runtime.h>
#include <cuda_bf16.h>
#include <cstdint>
#include <math.h>

#define B_  4096
#define C_  128
#define T_  10
#define J_  22
#define N_  220
#define H_  128
#define NTHREADS 512
#define XS  264      // X smem row stride in bf16 (224 used + pad; stride keeps LDSM conflict-free)

static const long long SA_TOTAL = (long long)B_ * T_ * J_ * J_;   // 19,824,640
static const long long TA_TOTAL = (long long)B_ * J_ * T_ * T_;   //  9,011,200

// smem byte offsets
#define OFF_XHI 0                    // 128 x 264 bf16 = 67584 ; reused as output stage
#define OFF_XLO 67584
#define OFF_SD  135168               // sS,dS,sT,dT : 4 x 256 f32 = 4096
#define SMEM_TOTAL 139264

// W in mma-fragment layout: [br][pass(hi/lo)][mt 0..7][kc 0..7][lane 0..31] -> uint4{a0,a1,a2,a3}
__device__ __align__(16) uint4 g_Wfrag[2][2][8][8][32];

__device__ __forceinline__ uint32_t smem_u32(const void* p) {
    uint32_t a;
    asm("{ .reg .u64 t; cvta.to.shared.u64 t, %1; cvt.u32.u64 %0, t; }" : "=r"(a) : "l"(p));
    return a;
}

__device__ __forceinline__ void bf16_split2(float x, float y, uint32_t& hp, uint32_t& lp) {
    __nv_bfloat16 hx = __float2bfloat16(x);
    __nv_bfloat16 hy = __float2bfloat16(y);
    __nv_bfloat16 lx = __float2bfloat16(x - __bfloat162float(hx));
    __nv_bfloat16 ly = __float2bfloat16(y - __bfloat162float(hy));
    __nv_bfloat162 Hh; Hh.x = hx; Hh.y = hy;
    __nv_bfloat162 Ll; Ll.x = lx; Ll.y = ly;
    hp = *reinterpret_cast<uint32_t*>(&Hh);
    lp = *reinterpret_cast<uint32_t*>(&Ll);
}

// setup: W[h][c] fp32 -> fragment-layout bf16 hi/lo images
// a0: (r0,c0..c0+1)  a1: (r0+8,c0..)  a2: (r0,c1..)  a3: (r0+8,c1..)
__global__ void __launch_bounds__(512, 1)
setup_w_kernel(const float* __restrict__ W_s, const float* __restrict__ W_t)
{
    const int t = blockIdx.x * 512 + threadIdx.x;   // 0..8191
    const int lane = t & 31;
    const int kc   = (t >> 5) & 7;
    const int mt   = (t >> 8) & 7;
    const int br   = (t >> 11) & 1;
    const float* W = br ? W_t : W_s;

    const int g = lane >> 2, q = lane & 3;
    const int r0 = mt * 16 + g, r1 = r0 + 8;
    const int c0 = kc * 16 + q * 2, c1 = c0 + 8;

    uint32_t h0, l0, h1, l1, h2, l2, h3, l3;
    bf16_split2(W[r0 * C_ + c0], W[r0 * C_ + c0 + 1], h0, l0);
    bf16_split2(W[r1 * C_ + c0], W[r1 * C_ + c0 + 1], h1, l1);
    bf16_split2(W[r0 * C_ + c1], W[r0 * C_ + c1 + 1], h2, l2);
    bf16_split2(W[r1 * C_ + c1], W[r1 * C_ + c1 + 1], h3, l3);

    g_Wfrag[br][0][mt][kc][lane] = make_uint4(h0, h1, h2, h3);
    g_Wfrag[br][1][mt][kc][lane] = make_uint4(l0, l1, l2, l3);
}

#define LDSM_X4T(r0,r1,r2,r3,addr) \
    asm volatile("ldmatrix.sync.aligned.m8n8.x4.trans.shared.b16 {%0,%1,%2,%3}, [%4];" \
                 : "=r"(r0), "=r"(r1), "=r"(r2), "=r"(r3) : "r"(addr))
#define LDSM_X2T(r0,r1,addr) \
    asm volatile("ldmatrix.sync.aligned.m8n8.x2.trans.shared.b16 {%0,%1}, [%2];" \
                 : "=r"(r0), "=r"(r1) : "r"(addr))
#define MMA16816(acc,a,b0,b1) \
    asm volatile("mma.sync.aligned.m16n8k16.row.col.f32.bf16.bf16.f32 " \
                 "{%0,%1,%2,%3},{%4,%5,%6,%7},{%8,%9},{%0,%1,%2,%3};" \
                 : "+f"((acc)[0]), "+f"((acc)[1]), "+f"((acc)[2]), "+f"((acc)[3]) \
                 : "r"((a).x), "r"((a).y), "r"((a).z), "r"((a).w), "r"(b0), "r"(b1))

// 3-pass split-bf16 GEMM (128h x 224n x 128c); A frags from global, B from smem
__device__ __forceinline__ void mainloop(
    uint32_t sb, int br, int mw, int nw, int lane, float acc[2][7][4])
{
    #pragma unroll
    for (int mt = 0; mt < 2; ++mt)
        #pragma unroll
        for (int nt = 0; nt < 7; ++nt)
            #pragma unroll
            for (int p = 0; p < 4; ++p) acc[mt][nt][p] = 0.f;

    // B x4.trans lane addressing: matrix m4 = lane>>3 : krow = (m4&1)*8 + r, col += (m4>>1)*8
    const int m4 = lane >> 3, r4 = lane & 7;
    const uint32_t bo4 = (uint32_t)((((m4 & 1) * 8 + r4) * XS + nw * 56 + (m4 >> 1) * 8) * 2);
    // x2 lane addressing (lanes 0..15): krow = (lane>>3)*8 + (lane&7)
    const uint32_t bo2 = (uint32_t)(((((lane >> 3) & 1) * 8 + (lane & 7)) * XS + nw * 56 + 48) * 2);

    const uint32_t BH4 = sb + OFF_XHI + bo4, BL4 = sb + OFF_XLO + bo4;
    const uint32_t BH2 = sb + OFF_XHI + bo2, BL2 = sb + OFF_XLO + bo2;

    const uint4* fh = &g_Wfrag[br][0][mw * 2][0][lane];   // +32 per kc, +256 per mt
    const uint4* fl = &g_Wfrag[br][1][mw * 2][0][lane];

    uint4 AH0 = fh[0], AH1 = fh[256], AL0 = fl[0], AL1 = fl[256];

    #pragma unroll 1
    for (int kc = 0; kc < 8; ++kc) {
        uint32_t bh[7][2], bl[7][2];
        const uint32_t kb = (uint32_t)(kc * 16 * XS * 2);
        LDSM_X4T(bh[0][0], bh[0][1], bh[1][0], bh[1][1], BH4 + kb);
        LDSM_X4T(bh[2][0], bh[2][1], bh[3][0], bh[3][1], BH4 + kb + 32);
        LDSM_X4T(bh[4][0], bh[4][1], bh[5][0], bh[5][1], BH4 + kb + 64);
        LDSM_X2T(bh[6][0], bh[6][1], BH2 + kb);
        LDSM_X4T(bl[0][0], bl[0][1], bl[1][0], bl[1][1], BL4 + kb);
        LDSM_X4T(bl[2][0], bl[2][1], bl[3][0], bl[3][1], BL4 + kb + 32);
        LDSM_X4T(bl[4][0], bl[4][1], bl[5][0], bl[5][1], BL4 + kb + 64);
        LDSM_X2T(bl[6][0], bl[6][1], BL2 + kb);

        uint4 nAH0, nAH1, nAL0, nAL1;
        if (kc < 7) {
            nAH0 = fh[(kc + 1) * 32];
            nAH1 = fh[256 + (kc + 1) * 32];
            nAL0 = fl[(kc + 1) * 32];
            nAL1 = fl[256 + (kc + 1) * 32];
        }

        #pragma unroll
        for (int nt = 0; nt < 7; ++nt) {
            MMA16816(acc[0][nt], AH0, bh[nt][0], bh[nt][1]);
            MMA16816(acc[1][nt], AH1, bh[nt][0], bh[nt][1]);
            MMA16816(acc[0][nt], AL0, bh[nt][0], bh[nt][1]);
            MMA16816(acc[1][nt], AL1, bh[nt][0], bh[nt][1]);
            MMA16816(acc[0][nt], AH0, bl[nt][0], bl[nt][1]);
            MMA16816(acc[1][nt], AH1, bl[nt][0], bl[nt][1]);
        }
        if (kc < 7) { AH0 = nAH0; AH1 = nAH1; AL0 = nAL0; AL1 = nAL1; }
    }
}

__device__ __forceinline__ void epilogue(
    float acc[2][7][4], const float* __restrict__ aS, const float* __restrict__ aD,
    float* __restrict__ sArr, float* __restrict__ dArr, int mw, int nw, int lane)
{
    const int g = lane >> 2, q = lane & 3;
    const float as00 = aS[mw * 32 + g],      as08 = aS[mw * 32 + 8 + g];
    const float as10 = aS[mw * 32 + 16 + g], as18 = aS[mw * 32 + 24 + g];
    const float ad00 = aD[mw * 32 + g],      ad08 = aD[mw * 32 + 8 + g];
    const float ad10 = aD[mw * 32 + 16 + g], ad18 = aD[mw * 32 + 24 + g];

    #pragma unroll
    for (int nt = 0; nt < 7; ++nt) {
        float L00, L01, L02, L03, L10, L11, L12, L13, v;
        v = acc[0][nt][0]; L00 = fmaxf(v, 0.2f * v);
        v = acc[0][nt][1]; L01 = fmaxf(v, 0.2f * v);
        v = acc[0][nt][2]; L02 = fmaxf(v, 0.2f * v);
        v = acc[0][nt][3]; L03 = fmaxf(v, 0.2f * v);
        v = acc[1][nt][0]; L10 = fmaxf(v, 0.2f * v);
        v = acc[1][nt][1]; L11 = fmaxf(v, 0.2f * v);
        v = acc[1][nt][2]; L12 = fmaxf(v, 0.2f * v);
        v = acc[1][nt][3]; L13 = fmaxf(v, 0.2f * v);
        float ss0 = as00 * L00 + as08 * L02 + as10 * L10 + as18 * L12;
        float ss1 = as00 * L01 + as08 * L03 + as10 * L11 + as18 * L13;
        float dd0 = ad00 * L00 + ad08 * L02 + ad10 * L10 + ad18 * L12;
        float dd1 = ad00 * L01 + ad08 * L03 + ad10 * L11 + ad18 * L13;
        #pragma unroll
        for (int m = 4; m <= 16; m <<= 1) {
            ss0 += __shfl_xor_sync(0xffffffffu, ss0, m);
            ss1 += __shfl_xor_sync(0xffffffffu, ss1, m);
            dd0 += __shfl_xor_sync(0xffffffffu, dd0, m);
            dd1 += __shfl_xor_sync(0xffffffffu, dd1, m);
        }
        if (g == 0) {
            const int n0 = nw * 56 + nt * 8 + q * 2;
            atomicAdd(&sArr[n0],     ss0);
            atomicAdd(&sArr[n0 + 1], ss1);
            atomicAdd(&dArr[n0],     dd0);
            atomicAdd(&dArr[n0 + 1], dd1);
        }
    }
}

__global__ void __launch_bounds__(NTHREADS, 1)
dms_st_attention_kernel(
    const float* __restrict__ src,
    const float* __restrict__ a_src_s,
    const float* __restrict__ a_dst_s,
    const float* __restrict__ a_src_t,
    const float* __restrict__ a_dst_t,
    const float* __restrict__ sa_bias,
    const float* __restrict__ ta_bias,
    float* __restrict__ out,
    long long out_size)
{
    extern __shared__ char smc[];
    const uint32_t sb = smem_u32(smc);
    const int tid  = threadIdx.x;
    const int lane = tid & 31;
    const int wid  = tid >> 5;
    const int b    = blockIdx.x;
    const int mw   = wid & 3;
    const int nw   = wid >> 2;

    float* sS = (float*)(smc + OFF_SD);
    float* dS = sS + 256;
    float* sT = dS + 256;
    float* dT = sT + 256;

    sS[tid] = 0.f; sS[tid + 512] = 0.f;

    // ---- X convert: src[b] [128c][220n] fp32 -> Xhi/Xlo bf16 (stride XS) ----
    {
        const float4* g = (const float4*)(src + (size_t)b * (C_ * N_));
        #pragma unroll
        for (int u = 0; u < 14; ++u) {
            const int idx = u * 512 + tid;
            if (u == 13 && idx >= 7040) break;
            const int c = idx / 55, p = idx - c * 55, n0 = p * 4;
            const float4 v = g[idx];
            uint32_t hp0, lp0, hp1, lp1;
            bf16_split2(v.x, v.y, hp0, lp0);
            bf16_split2(v.z, v.w, hp1, lp1);
            const int e = (c * XS + n0) * 2;
            *(uint2*)(smc + OFF_XHI + e) = make_uint2(hp0, hp1);
            *(uint2*)(smc + OFF_XLO + e) = make_uint2(lp0, lp1);
        }
        // zero pad cols 220..223 only
        if (tid < 256) {
            const int c = tid >> 1, pair = tid & 1;
            const int e = (c * XS + 220 + pair * 2) * 2;
            *(uint32_t*)(smc + OFF_XHI + e) = 0u;
            *(uint32_t*)(smc + OFF_XLO + e) = 0u;
        }
    }

    // L2 prefetch of next-wave CTA's src
    if (b + 148 < B_) {
        const char* nsrc = (const char*)(src + (size_t)(b + 148) * (C_ * N_));
        #pragma unroll
        for (int u = 0; u < 2; ++u) {
            const int line = tid + u * 512;
            if (line < 880)
                asm volatile("prefetch.global.L2 [%0];" :: "l"(nsrc + line * 128));
        }
    }
    __syncthreads();

    float acc[2][7][4];

    // ---- branch S -> epilogue -> branch T (no barriers needed between) ----
    mainloop(sb, 0, mw, nw, lane, acc);
    epilogue(acc, a_src_s, a_dst_s, sS, dS, mw, nw, lane);
    mainloop(sb, 1, mw, nw, lane, acc);
    epilogue(acc, a_src_t, a_dst_t, sT, dT, mw, nw, lane);
    __syncthreads();

    // ---- softmax + bias -> smem stage (X area dead now) ----
    float* sa_stage = (float*)(smc + OFF_XHI);            // 4840 floats
    float* ta_stage = sa_stage + 4840;                    // 2200 floats

    if (tid < N_) {                                       // warps 0..6: spatial
        const int r = tid;
        const int t = r / J_;
        const int i = r - t * J_;
        const float si = sS[r];
        const float* drow = dS + t * J_;
        float mx = -INFINITY;
        #pragma unroll
        for (int j = 0; j < J_; ++j) mx = fmaxf(mx, si + drow[j]);
        float ev[J_]; float sum = 0.f;
        #pragma unroll
        for (int j = 0; j < J_; ++j) { ev[j] = __expf(si + drow[j] - mx); sum += ev[j]; }
        const float inv = __fdividef(1.f, sum);
        float* o = sa_stage + r * J_;
        const float* bias = sa_bias + i * J_;
        #pragma unroll
        for (int j = 0; j < J_; ++j) o[j] = ev[j] * inv + bias[j];
    } else if (tid >= 256 && tid < 256 + N_) {            // warps 8..14: temporal
        const int r  = tid - 256;
        const int j  = r / T_;
        const int ti = r - j * T_;
        const float si = sT[ti * J_ + j];
        float mx = -INFINITY;
        #pragma unroll
        for (int tj = 0; tj < T_; ++tj) mx = fmaxf(mx, si + dT[tj * J_ + j]);
        float ev[T_]; float sum = 0.f;
        #pragma unroll
        for (int tj = 0; tj < T_; ++tj) { ev[tj] = __expf(si + dT[tj * J_ + j] - mx); sum += ev[tj]; }
        const float inv = __fdividef(1.f, sum);
        float* o = ta_stage + r * T_;
        const float* bias = ta_bias + ti * T_;
        #pragma unroll
        for (int tj = 0; tj < T_; ++tj) o[tj] = ev[tj] * inv + bias[tj];
    }
    __syncthreads();

    // ---- coalesced copy-out ----
    {
        const float4* s4 = (const float4*)sa_stage;
        float4* o4 = (float4*)(out + (size_t)b * 4840);
        #pragma unroll
        for (int u = 0; u < 3; ++u) {
            const int i = u * 512 + tid;
            if (i < 1210) o4[i] = s4[i];
        }
        const float4* t4 = (const float4*)ta_stage;
        float4* p4 = (float4*)(out + SA_TOTAL + (size_t)b * 2200);
        #pragma unroll
        for (int u = 0; u < 2; ++u) {
            const int i = u * 512 + tid;
            if (i < 550) p4[i] = t4[i];
        }
    }

    if (b == 0) {
        for (long long i = SA_TOTAL + TA_TOTAL + tid; i < out_size; i += NTHREADS)
            out[i] = 0.f;
    }
}

extern "C" void kernel_launch(void* const* d_in, const int* in_sizes, int n_in,
                              void* d_out, int out_size)
{
    const float* src     = (const float*)d_in[0];
    const float* W_s     = (const float*)d_in[1];
    const float* a_src_s = (const float*)d_in[2];
    const float* a_dst_s = (const float*)d_in[3];
    const float* W_t     = (const float*)d_in[4];
    const float* a_src_t = (const float*)d_in[5];
    const float* a_dst_t = (const float*)d_in[6];
    const float* sa_bias = (const float*)d_in[7];
    const float* ta_bias = (const float*)d_in[8];
    float* out = (float*)d_out;

    cudaFuncSetAttribute(dms_st_attention_kernel,
                         cudaFuncAttributeMaxDynamicSharedMemorySize, SMEM_TOTAL);

    setup_w_kernel<<<16, 512>>>(W_s, W_t);
    dms_st_attention_kernel<<<B_, NTHREADS, SMEM_TOTAL>>>(
        src, a_src_s, a_dst_s, a_src_t, a_dst_t,
        sa_bias, ta_bias, out, (long long)out_size);
}

// round 9
// speedup vs baseline: 3.9947x; 1.0135x over previous
#include <cuda_runtime.h>
#include <cuda_bf16.h>
#include <cstdint>
#include <math.h>

#define B_  4096
#define C_  128
#define T_  10
#define J_  22
#define N_  220
#define H_  128
#define NTHREADS 512
#define XS  264      // X smem row stride in bf16

static const long long SA_TOTAL = (long long)B_ * T_ * J_ * J_;   // 19,824,640
static const long long TA_TOTAL = (long long)B_ * J_ * T_ * T_;   //  9,011,200

// smem byte offsets
#define OFF_XHI 0                    // 128 x 264 bf16 = 67584 ; reused as output stage
#define OFF_XLO 67584
#define OFF_SD  135168               // sS,dS,sT,dT : 4 x 256 f32 = 4096
#define SMEM_TOTAL 139264

// W in mma-fragment layout: [br][pass(hi/lo)][mt 0..7][kc 0..7][lane 0..31] -> uint4{a0,a1,a2,a3}
__device__ __align__(16) uint4 g_Wfrag[2][2][8][8][32];

__device__ __forceinline__ uint32_t smem_u32(const void* p) {
    uint32_t a;
    asm("{ .reg .u64 t; cvta.to.shared.u64 t, %1; cvt.u32.u64 %0, t; }" : "=r"(a) : "l"(p));
    return a;
}

__device__ __forceinline__ void bf16_split2(float x, float y, uint32_t& hp, uint32_t& lp) {
    __nv_bfloat16 hx = __float2bfloat16(x);
    __nv_bfloat16 hy = __float2bfloat16(y);
    __nv_bfloat16 lx = __float2bfloat16(x - __bfloat162float(hx));
    __nv_bfloat16 ly = __float2bfloat16(y - __bfloat162float(hy));
    __nv_bfloat162 Hh; Hh.x = hx; Hh.y = hy;
    __nv_bfloat162 Ll; Ll.x = lx; Ll.y = ly;
    hp = *reinterpret_cast<uint32_t*>(&Hh);
    lp = *reinterpret_cast<uint32_t*>(&Ll);
}

// fast truncation split: hi = top 16 bits (1 PRMT per pair), lo = exact residual, RN-packed
__device__ __forceinline__ void split_trunc2(float x, float y, uint32_t& hp, uint32_t& lp) {
    const uint32_t xb = __float_as_uint(x), yb = __float_as_uint(y);
    asm("prmt.b32 %0, %1, %2, 0x7632;" : "=r"(hp) : "r"(xb), "r"(yb));
    const float lx = x - __uint_as_float(xb & 0xFFFF0000u);
    const float ly = y - __uint_as_float(yb & 0xFFFF0000u);
    asm("cvt.rn.bf16x2.f32 %0, %1, %2;" : "=r"(lp) : "f"(ly), "f"(lx));
}

// setup: W[h][c] fp32 -> fragment-layout bf16 hi/lo images (RN split; high accuracy, runs once)
__global__ void __launch_bounds__(512, 1)
setup_w_kernel(const float* __restrict__ W_s, const float* __restrict__ W_t)
{
    const int t = blockIdx.x * 512 + threadIdx.x;   // 0..8191
    const int lane = t & 31;
    const int kc   = (t >> 5) & 7;
    const int mt   = (t >> 8) & 7;
    const int br   = (t >> 11) & 1;
    const float* W = br ? W_t : W_s;

    const int g = lane >> 2, q = lane & 3;
    const int r0 = mt * 16 + g, r1 = r0 + 8;
    const int c0 = kc * 16 + q * 2, c1 = c0 + 8;

    uint32_t h0, l0, h1, l1, h2, l2, h3, l3;
    bf16_split2(W[r0 * C_ + c0], W[r0 * C_ + c0 + 1], h0, l0);
    bf16_split2(W[r1 * C_ + c0], W[r1 * C_ + c0 + 1], h1, l1);
    bf16_split2(W[r0 * C_ + c1], W[r0 * C_ + c1 + 1], h2, l2);
    bf16_split2(W[r1 * C_ + c1], W[r1 * C_ + c1 + 1], h3, l3);

    g_Wfrag[br][0][mt][kc][lane] = make_uint4(h0, h1, h2, h3);
    g_Wfrag[br][1][mt][kc][lane] = make_uint4(l0, l1, l2, l3);
}

#define LDSM_X4T(r0,r1,r2,r3,addr) \
    asm volatile("ldmatrix.sync.aligned.m8n8.x4.trans.shared.b16 {%0,%1,%2,%3}, [%4];" \
                 : "=r"(r0), "=r"(r1), "=r"(r2), "=r"(r3) : "r"(addr))
#define LDSM_X2T(r0,r1,addr) \
    asm volatile("ldmatrix.sync.aligned.m8n8.x2.trans.shared.b16 {%0,%1}, [%2];" \
                 : "=r"(r0), "=r"(r1) : "r"(addr))
#define MMA16816(acc,a,b0,b1) \
    asm volatile("mma.sync.aligned.m16n8k16.row.col.f32.bf16.bf16.f32 " \
                 "{%0,%1,%2,%3},{%4,%5,%6,%7},{%8,%9},{%0,%1,%2,%3};" \
                 : "+f"((acc)[0]), "+f"((acc)[1]), "+f"((acc)[2]), "+f"((acc)[3]) \
                 : "r"((a).x), "r"((a).y), "r"((a).z), "r"((a).w), "r"(b0), "r"(b1))

// 3-pass split-bf16 GEMM (128h x 224n x 128c); A frags from global, B from smem
__device__ __forceinline__ void mainloop(
    uint32_t sb, int br, int mw, int nw, int lane, float acc[2][7][4])
{
    #pragma unroll
    for (int mt = 0; mt < 2; ++mt)
        #pragma unroll
        for (int nt = 0; nt < 7; ++nt)
            #pragma unroll
            for (int p = 0; p < 4; ++p) acc[mt][nt][p] = 0.f;

    const int m4 = lane >> 3, r4 = lane & 7;
    const uint32_t bo4 = (uint32_t)((((m4 & 1) * 8 + r4) * XS + nw * 56 + (m4 >> 1) * 8) * 2);
    const uint32_t bo2 = (uint32_t)(((((lane >> 3) & 1) * 8 + (lane & 7)) * XS + nw * 56 + 48) * 2);

    const uint32_t BH4 = sb + OFF_XHI + bo4, BL4 = sb + OFF_XLO + bo4;
    const uint32_t BH2 = sb + OFF_XHI + bo2, BL2 = sb + OFF_XLO + bo2;

    const uint4* fh = &g_Wfrag[br][0][mw * 2][0][lane];   // +32 per kc, +256 per mt
    const uint4* fl = &g_Wfrag[br][1][mw * 2][0][lane];

    uint4 AH0 = fh[0], AH1 = fh[256], AL0 = fl[0], AL1 = fl[256];

    #pragma unroll 1
    for (int kc = 0; kc < 8; ++kc) {
        uint32_t bh[7][2], bl[7][2];
        const uint32_t kb = (uint32_t)(kc * 16 * XS * 2);
        LDSM_X4T(bh[0][0], bh[0][1], bh[1][0], bh[1][1], BH4 + kb);
        LDSM_X4T(bh[2][0], bh[2][1], bh[3][0], bh[3][1], BH4 + kb + 32);
        LDSM_X4T(bh[4][0], bh[4][1], bh[5][0], bh[5][1], BH4 + kb + 64);
        LDSM_X2T(bh[6][0], bh[6][1], BH2 + kb);
        LDSM_X4T(bl[0][0], bl[0][1], bl[1][0], bl[1][1], BL4 + kb);
        LDSM_X4T(bl[2][0], bl[2][1], bl[3][0], bl[3][1], BL4 + kb + 32);
        LDSM_X4T(bl[4][0], bl[4][1], bl[5][0], bl[5][1], BL4 + kb + 64);
        LDSM_X2T(bl[6][0], bl[6][1], BL2 + kb);

        uint4 nAH0, nAH1, nAL0, nAL1;
        if (kc < 7) {
            nAH0 = fh[(kc + 1) * 32];
            nAH1 = fh[256 + (kc + 1) * 32];
            nAL0 = fl[(kc + 1) * 32];
            nAL1 = fl[256 + (kc + 1) * 32];
        }

        #pragma unroll
        for (int nt = 0; nt < 7; ++nt) {
            MMA16816(acc[0][nt], AH0, bh[nt][0], bh[nt][1]);
            MMA16816(acc[1][nt], AH1, bh[nt][0], bh[nt][1]);
            MMA16816(acc[0][nt], AL0, bh[nt][0], bh[nt][1]);
            MMA16816(acc[1][nt], AL1, bh[nt][0], bh[nt][1]);
            MMA16816(acc[0][nt], AH0, bl[nt][0], bl[nt][1]);
            MMA16816(acc[1][nt], AH1, bl[nt][0], bl[nt][1]);
        }
        if (kc < 7) { AH0 = nAH0; AH1 = nAH1; AL0 = nAL0; AL1 = nAL1; }
    }
}

__device__ __forceinline__ void epilogue(
    float acc[2][7][4], const float* __restrict__ aS, const float* __restrict__ aD,
    float* __restrict__ sArr, float* __restrict__ dArr, int mw, int nw, int lane)
{
    const int g = lane >> 2, q = lane & 3;
    const float as00 = aS[mw * 32 + g],      as08 = aS[mw * 32 + 8 + g];
    const float as10 = aS[mw * 32 + 16 + g], as18 = aS[mw * 32 + 24 + g];
    const float ad00 = aD[mw * 32 + g],      ad08 = aD[mw * 32 + 8 + g];
    const float ad10 = aD[mw * 32 + 16 + g], ad18 = aD[mw * 32 + 24 + g];

    #pragma unroll
    for (int nt = 0; nt < 7; ++nt) {
        float L00, L01, L02, L03, L10, L11, L12, L13, v;
        v = acc[0][nt][0]; L00 = fmaxf(v, 0.2f * v);
        v = acc[0][nt][1]; L01 = fmaxf(v, 0.2f * v);
        v = acc[0][nt][2]; L02 = fmaxf(v, 0.2f * v);
        v = acc[0][nt][3]; L03 = fmaxf(v, 0.2f * v);
        v = acc[1][nt][0]; L10 = fmaxf(v, 0.2f * v);
        v = acc[1][nt][1]; L11 = fmaxf(v, 0.2f * v);
        v = acc[1][nt][2]; L12 = fmaxf(v, 0.2f * v);
        v = acc[1][nt][3]; L13 = fmaxf(v, 0.2f * v);
        float ss0 = as00 * L00 + as08 * L02 + as10 * L10 + as18 * L12;
        float ss1 = as00 * L01 + as08 * L03 + as10 * L11 + as18 * L13;
        float dd0 = ad00 * L00 + ad08 * L02 + ad10 * L10 + ad18 * L12;
        float dd1 = ad00 * L01 + ad08 * L03 + ad10 * L11 + ad18 * L13;
        #pragma unroll
        for (int m = 4; m <= 16; m <<= 1) {
            ss0 += __shfl_xor_sync(0xffffffffu, ss0, m);
            ss1 += __shfl_xor_sync(0xffffffffu, ss1, m);
            dd0 += __shfl_xor_sync(0xffffffffu, dd0, m);
            dd1 += __shfl_xor_sync(0xffffffffu, dd1, m);
        }
        if (g == 0) {
            const int n0 = nw * 56 + nt * 8 + q * 2;
            atomicAdd(&sArr[n0],     ss0);
            atomicAdd(&sArr[n0 + 1], ss1);
            atomicAdd(&dArr[n0],     dd0);
            atomicAdd(&dArr[n0 + 1], dd1);
        }
    }
}

__device__ __forceinline__ void conv_store(char* smc, int idx, float4 v) {
    const int c = idx / 55, p = idx - c * 55, n0 = p * 4;
    uint32_t hp0, lp0, hp1, lp1;
    split_trunc2(v.x, v.y, hp0, lp0);
    split_trunc2(v.z, v.w, hp1, lp1);
    const int e = (c * XS + n0) * 2;
    *(uint2*)(smc + OFF_XHI + e) = make_uint2(hp0, hp1);
    *(uint2*)(smc + OFF_XLO + e) = make_uint2(lp0, lp1);
}

__global__ void __launch_bounds__(NTHREADS, 1)
dms_st_attention_kernel(
    const float* __restrict__ src,
    const float* __restrict__ a_src_s,
    const float* __restrict__ a_dst_s,
    const float* __restrict__ a_src_t,
    const float* __restrict__ a_dst_t,
    const float* __restrict__ sa_bias,
    const float* __restrict__ ta_bias,
    float* __restrict__ out,
    long long out_size)
{
    extern __shared__ char smc[];
    const uint32_t sb = smem_u32(smc);
    const int tid  = threadIdx.x;
    const int lane = tid & 31;
    const int wid  = tid >> 5;
    const int b    = blockIdx.x;
    const int mw   = wid & 3;
    const int nw   = wid >> 2;

    float* sS = (float*)(smc + OFF_SD);
    float* dS = sS + 256;
    float* sT = dS + 256;
    float* dT = sT + 256;

    sS[tid] = 0.f; sS[tid + 512] = 0.f;

    // ---- X convert: batched loads (MLP=7) + truncation split ----
    {
        const float4* g = (const float4*)(src + (size_t)b * (C_ * N_));  // 7040 float4
        float4 v[7];
        #pragma unroll
        for (int u = 0; u < 7; ++u) v[u] = g[u * 512 + tid];
        #pragma unroll
        for (int u = 0; u < 7; ++u) conv_store(smc, u * 512 + tid, v[u]);
        #pragma unroll
        for (int u = 0; u < 7; ++u) {
            const int idx = (7 + u) * 512 + tid;
            if (u < 6 || idx < 7040) v[u] = g[idx];
        }
        #pragma unroll
        for (int u = 0; u < 7; ++u) {
            const int idx = (7 + u) * 512 + tid;
            if (u < 6 || idx < 7040) conv_store(smc, idx, v[u]);
        }
        // zero pad cols 220..223
        if (tid < 256) {
            const int c = tid >> 1, pair = tid & 1;
            const int e = (c * XS + 220 + pair * 2) * 2;
            *(uint32_t*)(smc + OFF_XHI + e) = 0u;
            *(uint32_t*)(smc + OFF_XLO + e) = 0u;
        }
    }

    // L2 prefetch of next-wave CTA's src
    if (b + 148 < B_) {
        const char* nsrc = (const char*)(src + (size_t)(b + 148) * (C_ * N_));
        #pragma unroll
        for (int u = 0; u < 2; ++u) {
            const int line = tid + u * 512;
            if (line < 880)
                asm volatile("prefetch.global.L2 [%0];" :: "l"(nsrc + line * 128));
        }
    }
    __syncthreads();

    float acc[2][7][4];

    // ---- branch S -> epilogue -> branch T (no barriers needed between) ----
    mainloop(sb, 0, mw, nw, lane, acc);
    epilogue(acc, a_src_s, a_dst_s, sS, dS, mw, nw, lane);
    mainloop(sb, 1, mw, nw, lane, acc);
    epilogue(acc, a_src_t, a_dst_t, sT, dT, mw, nw, lane);
    __syncthreads();

    // ---- softmax + bias -> smem stage (X area dead now) ----
    float* sa_stage = (float*)(smc + OFF_XHI);            // 4840 floats
    float* ta_stage = sa_stage + 4840;                    // 2200 floats

    if (tid < N_) {                                       // warps 0..6: spatial
        const int r = tid;
        const int t = r / J_;
        const int i = r - t * J_;
        const float si = sS[r];
        const float* drow = dS + t * J_;
        float mx = -INFINITY;
        #pragma unroll
        for (int j = 0; j < J_; ++j) mx = fmaxf(mx, si + drow[j]);
        float ev[J_]; float sum = 0.f;
        #pragma unroll
        for (int j = 0; j < J_; ++j) { ev[j] = __expf(si + drow[j] - mx); sum += ev[j]; }
        const float inv = __fdividef(1.f, sum);
        float* o = sa_stage + r * J_;
        const float* bias = sa_bias + i * J_;
        #pragma unroll
        for (int j = 0; j < J_; ++j) o[j] = ev[j] * inv + bias[j];
    } else if (tid >= 256 && tid < 256 + N_) {            // warps 8..14: temporal
        const int r  = tid - 256;
        const int j  = r / T_;
        const int ti = r - j * T_;
        const float si = sT[ti * J_ + j];
        float mx = -INFINITY;
        #pragma unroll
        for (int tj = 0; tj < T_; ++tj) mx = fmaxf(mx, si + dT[tj * J_ + j]);
        float ev[T_]; float sum = 0.f;
        #pragma unroll
        for (int tj = 0; tj < T_; ++tj) { ev[tj] = __expf(si + dT[tj * J_ + j] - mx); sum += ev[tj]; }
        const float inv = __fdividef(1.f, sum);
        float* o = ta_stage + r * T_;
        const float* bias = ta_bias + ti * T_;
        #pragma unroll
        for (int tj = 0; tj < T_; ++tj) o[tj] = ev[tj] * inv + bias[tj];
    }
    __syncthreads();

    // ---- coalesced copy-out ----
    {
        const float4* s4 = (const float4*)sa_stage;
        float4* o4 = (float4*)(out + (size_t)b * 4840);
        #pragma unroll
        for (int u = 0; u < 3; ++u) {
            const int i = u * 512 + tid;
            if (i < 1210) o4[i] = s4[i];
        }
        const float4* t4 = (const float4*)ta_stage;
        float4* p4 = (float4*)(out + SA_TOTAL + (size_t)b * 2200);
        #pragma unroll
        for (int u = 0; u < 2; ++u) {
            const int i = u * 512 + tid;
            if (i < 550) p4[i] = t4[i];
        }
    }

    if (b == 0) {
        for (long long i = SA_TOTAL + TA_TOTAL + tid; i < out_size; i += NTHREADS)
            out[i] = 0.f;
    }
}

extern "C" void kernel_launch(void* const* d_in, const int* in_sizes, int n_in,
                              void* d_out, int out_size)
{
    const float* src     = (const float*)d_in[0];
    const float* W_s     = (const float*)d_in[1];
    const float* a_src_s = (const float*)d_in[2];
    const float* a_dst_s = (const float*)d_in[3];
    const float* W_t     = (const float*)d_in[4];
    const float* a_src_t = (const float*)d_in[5];
    const float* a_dst_t = (const float*)d_in[6];
    const float* sa_bias = (const float*)d_in[7];
    const float* ta_bias = (const float*)d_in[8];
    float* out = (float*)d_out;

    cudaFuncSetAttribute(dms_st_attention_kernel,
                         cudaFuncAttributeMaxDynamicSharedMemorySize, SMEM_TOTAL);

    setup_w_kernel<<<16, 512>>>(W_s, W_t);
    dms_st_attention_kernel<<<B_, NTHREADS, SMEM_TOTAL>>>(
        src, a_src_s, a_dst_s, a_src_t, a_dst_t,
        sa_bias, ta_bias, out, (long long)out_size);
}

// round 10
// speedup vs baseline: 6.5593x; 1.6420x over previous
#include <cuda_runtime.h>
#include <cuda_fp16.h>
#include <cstdint>
#include <math.h>

#define B_  4096
#define C_  128
#define T_  10
#define J_  22
#define N_  220
#define H_  128
#define NTHREADS 512
#define XS  264      // X smem row stride in fp16 elements (conflict-free for ldmatrix)

static const long long SA_TOTAL = (long long)B_ * T_ * J_ * J_;   // 19,824,640
static const long long TA_TOTAL = (long long)B_ * J_ * T_ * T_;   //  9,011,200

// smem byte offsets
#define OFF_X   0                    // 128 x 264 fp16 = 67584 ; reused as output stage
#define OFF_SD  67584                // sS,dS,sT,dT : 4 x 256 f32 = 4096
#define SMEM_TOTAL 71680

// W in mma-fragment layout (fp16): [br][mt 0..7][kc 0..7][lane 0..31] -> uint4{a0,a1,a2,a3}
__device__ __align__(16) uint4 g_Wfrag[2][8][8][32];

__device__ __forceinline__ uint32_t smem_u32(const void* p) {
    uint32_t a;
    asm("{ .reg .u64 t; cvta.to.shared.u64 t, %1; cvt.u32.u64 %0, t; }" : "=r"(a) : "l"(p));
    return a;
}

__device__ __forceinline__ uint32_t h2pack(float x, float y) {
    __half2 h = __floats2half2_rn(x, y);   // .x = x (low), .y = y (high)
    return *reinterpret_cast<uint32_t*>(&h);
}

// setup: W[h][c] fp32 -> fragment-layout fp16 images (runs once per replay)
__global__ void __launch_bounds__(512, 1)
setup_w_kernel(const float* __restrict__ W_s, const float* __restrict__ W_t)
{
    const int t = blockIdx.x * 512 + threadIdx.x;   // 0..8191
    const int lane = t & 31;
    const int kc   = (t >> 5) & 7;
    const int mt   = (t >> 8) & 7;
    const int br   = (t >> 11) & 1;
    const float* W = br ? W_t : W_s;

    const int g = lane >> 2, q = lane & 3;
    const int r0 = mt * 16 + g, r1 = r0 + 8;
    const int c0 = kc * 16 + q * 2, c1 = c0 + 8;

    const uint32_t a0 = h2pack(W[r0 * C_ + c0], W[r0 * C_ + c0 + 1]);
    const uint32_t a1 = h2pack(W[r1 * C_ + c0], W[r1 * C_ + c0 + 1]);
    const uint32_t a2 = h2pack(W[r0 * C_ + c1], W[r0 * C_ + c1 + 1]);
    const uint32_t a3 = h2pack(W[r1 * C_ + c1], W[r1 * C_ + c1 + 1]);

    g_Wfrag[br][mt][kc][lane] = make_uint4(a0, a1, a2, a3);
}

#define LDSM_X4T(r0,r1,r2,r3,addr) \
    asm volatile("ldmatrix.sync.aligned.m8n8.x4.trans.shared.b16 {%0,%1,%2,%3}, [%4];" \
                 : "=r"(r0), "=r"(r1), "=r"(r2), "=r"(r3) : "r"(addr))
#define LDSM_X2T(r0,r1,addr) \
    asm volatile("ldmatrix.sync.aligned.m8n8.x2.trans.shared.b16 {%0,%1}, [%2];" \
                 : "=r"(r0), "=r"(r1) : "r"(addr))
#define MMA16816F(acc,a,b0,b1) \
    asm volatile("mma.sync.aligned.m16n8k16.row.col.f32.f16.f16.f32 " \
                 "{%0,%1,%2,%3},{%4,%5,%6,%7},{%8,%9},{%0,%1,%2,%3};" \
                 : "+f"((acc)[0]), "+f"((acc)[1]), "+f"((acc)[2]), "+f"((acc)[3]) \
                 : "r"((a).x), "r"((a).y), "r"((a).z), "r"((a).w), "r"(b0), "r"(b1))

// single-pass fp16 GEMM (128h x 224n x 128c); A frags from global, B from smem
__device__ __forceinline__ void mainloop(
    uint32_t sb, int br, int mw, int nw, int lane, float acc[2][7][4])
{
    #pragma unroll
    for (int mt = 0; mt < 2; ++mt)
        #pragma unroll
        for (int nt = 0; nt < 7; ++nt)
            #pragma unroll
            for (int p = 0; p < 4; ++p) acc[mt][nt][p] = 0.f;

    const int m4 = lane >> 3, r4 = lane & 7;
    const uint32_t bo4 = (uint32_t)((((m4 & 1) * 8 + r4) * XS + nw * 56 + (m4 >> 1) * 8) * 2);
    const uint32_t bo2 = (uint32_t)(((((lane >> 3) & 1) * 8 + (lane & 7)) * XS + nw * 56 + 48) * 2);

    const uint32_t B4 = sb + OFF_X + bo4;
    const uint32_t B2 = sb + OFF_X + bo2;

    const uint4* fr = &g_Wfrag[br][mw * 2][0][lane];   // +32 per kc, +256 per mt

    uint4 A0 = fr[0], A1 = fr[256];

    #pragma unroll 1
    for (int kc = 0; kc < 8; ++kc) {
        uint32_t bh[7][2];
        const uint32_t kb = (uint32_t)(kc * 16 * XS * 2);
        LDSM_X4T(bh[0][0], bh[0][1], bh[1][0], bh[1][1], B4 + kb);
        LDSM_X4T(bh[2][0], bh[2][1], bh[3][0], bh[3][1], B4 + kb + 32);
        LDSM_X4T(bh[4][0], bh[4][1], bh[5][0], bh[5][1], B4 + kb + 64);
        LDSM_X2T(bh[6][0], bh[6][1], B2 + kb);

        uint4 nA0, nA1;
        if (kc < 7) {
            nA0 = fr[(kc + 1) * 32];
            nA1 = fr[256 + (kc + 1) * 32];
        }

        #pragma unroll
        for (int nt = 0; nt < 7; ++nt) {
            MMA16816F(acc[0][nt], A0, bh[nt][0], bh[nt][1]);
            MMA16816F(acc[1][nt], A1, bh[nt][0], bh[nt][1]);
        }
        if (kc < 7) { A0 = nA0; A1 = nA1; }
    }
}

__device__ __forceinline__ void epilogue(
    float acc[2][7][4], const float* __restrict__ aS, const float* __restrict__ aD,
    float* __restrict__ sArr, float* __restrict__ dArr, int mw, int nw, int lane)
{
    const int g = lane >> 2, q = lane & 3;
    const float as00 = aS[mw * 32 + g],      as08 = aS[mw * 32 + 8 + g];
    const float as10 = aS[mw * 32 + 16 + g], as18 = aS[mw * 32 + 24 + g];
    const float ad00 = aD[mw * 32 + g],      ad08 = aD[mw * 32 + 8 + g];
    const float ad10 = aD[mw * 32 + 16 + g], ad18 = aD[mw * 32 + 24 + g];

    #pragma unroll
    for (int nt = 0; nt < 7; ++nt) {
        float L00, L01, L02, L03, L10, L11, L12, L13, v;
        v = acc[0][nt][0]; L00 = fmaxf(v, 0.2f * v);
        v = acc[0][nt][1]; L01 = fmaxf(v, 0.2f * v);
        v = acc[0][nt][2]; L02 = fmaxf(v, 0.2f * v);
        v = acc[0][nt][3]; L03 = fmaxf(v, 0.2f * v);
        v = acc[1][nt][0]; L10 = fmaxf(v, 0.2f * v);
        v = acc[1][nt][1]; L11 = fmaxf(v, 0.2f * v);
        v = acc[1][nt][2]; L12 = fmaxf(v, 0.2f * v);
        v = acc[1][nt][3]; L13 = fmaxf(v, 0.2f * v);
        float ss0 = as00 * L00 + as08 * L02 + as10 * L10 + as18 * L12;
        float ss1 = as00 * L01 + as08 * L03 + as10 * L11 + as18 * L13;
        float dd0 = ad00 * L00 + ad08 * L02 + ad10 * L10 + ad18 * L12;
        float dd1 = ad00 * L01 + ad08 * L03 + ad10 * L11 + ad18 * L13;
        #pragma unroll
        for (int m = 4; m <= 16; m <<= 1) {
            ss0 += __shfl_xor_sync(0xffffffffu, ss0, m);
            ss1 += __shfl_xor_sync(0xffffffffu, ss1, m);
            dd0 += __shfl_xor_sync(0xffffffffu, dd0, m);
            dd1 += __shfl_xor_sync(0xffffffffu, dd1, m);
        }
        if (g == 0) {
            const int n0 = nw * 56 + nt * 8 + q * 2;
            atomicAdd(&sArr[n0],     ss0);
            atomicAdd(&sArr[n0 + 1], ss1);
            atomicAdd(&dArr[n0],     dd0);
            atomicAdd(&dArr[n0 + 1], dd1);
        }
    }
}

__device__ __forceinline__ void conv_store(char* smc, int idx, float4 v) {
    const int c = idx / 55, p = idx - c * 55, n0 = p * 4;
    const int e = (c * XS + n0) * 2;
    *(uint2*)(smc + OFF_X + e) = make_uint2(h2pack(v.x, v.y), h2pack(v.z, v.w));
}

__global__ void __launch_bounds__(NTHREADS, 1)
dms_st_attention_kernel(
    const float* __restrict__ src,
    const float* __restrict__ a_src_s,
    const float* __restrict__ a_dst_s,
    const float* __restrict__ a_src_t,
    const float* __restrict__ a_dst_t,
    const float* __restrict__ sa_bias,
    const float* __restrict__ ta_bias,
    float* __restrict__ out,
    long long out_size)
{
    extern __shared__ char smc[];
    const uint32_t sb = smem_u32(smc);
    const int tid  = threadIdx.x;
    const int lane = tid & 31;
    const int wid  = tid >> 5;
    const int b    = blockIdx.x;
    const int mw   = wid & 3;
    const int nw   = wid >> 2;

    float* sS = (float*)(smc + OFF_SD);
    float* dS = sS + 256;
    float* sT = dS + 256;
    float* dT = sT + 256;

    sS[tid] = 0.f; sS[tid + 512] = 0.f;

    // ---- X convert: fp32 -> fp16, batched loads ----
    {
        const float4* g = (const float4*)(src + (size_t)b * (C_ * N_));  // 7040 float4
        float4 v[7];
        #pragma unroll
        for (int u = 0; u < 7; ++u) v[u] = g[u * 512 + tid];
        #pragma unroll
        for (int u = 0; u < 7; ++u) conv_store(smc, u * 512 + tid, v[u]);
        #pragma unroll
        for (int u = 0; u < 7; ++u) {
            const int idx = (7 + u) * 512 + tid;
            if (u < 6 || idx < 7040) v[u] = g[idx];
        }
        #pragma unroll
        for (int u = 0; u < 7; ++u) {
            const int idx = (7 + u) * 512 + tid;
            if (u < 6 || idx < 7040) conv_store(smc, idx, v[u]);
        }
        // zero pad cols 220..223
        if (tid < 256) {
            const int c = tid >> 1, pair = tid & 1;
            const int e = (c * XS + 220 + pair * 2) * 2;
            *(uint32_t*)(smc + OFF_X + e) = 0u;
        }
    }

    // L2 prefetch of next-wave CTA's src
    if (b + 148 < B_) {
        const char* nsrc = (const char*)(src + (size_t)(b + 148) * (C_ * N_));
        #pragma unroll
        for (int u = 0; u < 2; ++u) {
            const int line = tid + u * 512;
            if (line < 880)
                asm volatile("prefetch.global.L2 [%0];" :: "l"(nsrc + line * 128));
        }
    }
    __syncthreads();

    float acc[2][7][4];

    // ---- branch S -> epilogue -> branch T (no barriers needed between) ----
    mainloop(sb, 0, mw, nw, lane, acc);
    epilogue(acc, a_src_s, a_dst_s, sS, dS, mw, nw, lane);
    mainloop(sb, 1, mw, nw, lane, acc);
    epilogue(acc, a_src_t, a_dst_t, sT, dT, mw, nw, lane);
    __syncthreads();

    // ---- softmax + bias -> smem stage (X area dead now) ----
    float* sa_stage = (float*)(smc + OFF_X);              // 4840 floats
    float* ta_stage = sa_stage + 4840;                    // 2200 floats

    if (tid < N_) {                                       // warps 0..6: spatial
        const int r = tid;
        const int t = r / J_;
        const int i = r - t * J_;
        const float si = sS[r];
        const float* drow = dS + t * J_;
        float mx = -INFINITY;
        #pragma unroll
        for (int j = 0; j < J_; ++j) mx = fmaxf(mx, si + drow[j]);
        float ev[J_]; float sum = 0.f;
        #pragma unroll
        for (int j = 0; j < J_; ++j) { ev[j] = __expf(si + drow[j] - mx); sum += ev[j]; }
        const float inv = __fdividef(1.f, sum);
        float* o = sa_stage + r * J_;
        const float* bias = sa_bias + i * J_;
        #pragma unroll
        for (int j = 0; j < J_; ++j) o[j] = ev[j] * inv + bias[j];
    } else if (tid >= 256 && tid < 256 + N_) {            // warps 8..14: temporal
        const int r  = tid - 256;
        const int j  = r / T_;
        const int ti = r - j * T_;
        const float si = sT[ti * J_ + j];
        float mx = -INFINITY;
        #pragma unroll
        for (int tj = 0; tj < T_; ++tj) mx = fmaxf(mx, si + dT[tj * J_ + j]);
        float ev[T_]; float sum = 0.f;
        #pragma unroll
        for (int tj = 0; tj < T_; ++tj) { ev[tj] = __expf(si + dT[tj * J_ + j] - mx); sum += ev[tj]; }
        const float inv = __fdividef(1.f, sum);
        float* o = ta_stage + r * T_;
        const float* bias = ta_bias + ti * T_;
        #pragma unroll
        for (int tj = 0; tj < T_; ++tj) o[tj] = ev[tj] * inv + bias[tj];
    }
    __syncthreads();

    // ---- coalesced copy-out ----
    {
        const float4* s4 = (const float4*)sa_stage;
        float4* o4 = (float4*)(out + (size_t)b * 4840);
        #pragma unroll
        for (int u = 0; u < 3; ++u) {
            const int i = u * 512 + tid;
            if (i < 1210) o4[i] = s4[i];
        }
        const float4* t4 = (const float4*)ta_stage;
        float4* p4 = (float4*)(out + SA_TOTAL + (size_t)b * 2200);
        #pragma unroll
        for (int u = 0; u < 2; ++u) {
            const int i = u * 512 + tid;
            if (i < 550) p4[i] = t4[i];
        }
    }

    if (b == 0) {
        for (long long i = SA_TOTAL + TA_TOTAL + tid; i < out_size; i += NTHREADS)
            out[i] = 0.f;
    }
}

extern "C" void kernel_launch(void* const* d_in, const int* in_sizes, int n_in,
                              void* d_out, int out_size)
{
    const float* src     = (const float*)d_in[0];
    const float* W_s     = (const float*)d_in[1];
    const float* a_src_s = (const float*)d_in[2];
    const float* a_dst_s = (const float*)d_in[3];
    const float* W_t     = (const float*)d_in[4];
    const float* a_src_t = (const float*)d_in[5];
    const float* a_dst_t = (const float*)d_in[6];
    const float* sa_bias = (const float*)d_in[7];
    const float* ta_bias = (const float*)d_in[8];
    float* out = (float*)d_out;

    cudaFuncSetAttribute(dms_st_attention_kernel,
                         cudaFuncAttributeMaxDynamicSharedMemorySize, SMEM_TOTAL);

    setup_w_kernel<<<16, 512>>>(W_s, W_t);
    dms_st_attention_kernel<<<B_, NTHREADS, SMEM_TOTAL>>>(
        src, a_src_s, a_dst_s, a_src_t, a_dst_t,
        sa_bias, ta_bias, out, (long long)out_size);
}